// round 13
// baseline (speedup 1.0000x reference)
#include <cuda_runtime.h>
#include <cuda_fp16.h>
#include <cstdint>

#define B_ 2
#define S_ 2048
#define D_ 768
#define H_ 12
#define DK_ 64
#define R_ 8
#define N_ 4096   // B_*S_
#define WSZ (D_ * D_)

// ---------------- scratch (static device globals; no allocation) ----------------
__device__ float  g_Aq[N_ * R_];
__device__ float  g_Av[N_ * R_];
__device__ __align__(256) __half g_Qadjh[(size_t)N_ * D_];
__device__ __align__(256) __half g_Vadjh[(size_t)N_ * D_];
__device__ __align__(256) __half g_keyh[(size_t)N_ * D_];
__device__ __align__(256) __half g_Wh[(size_t)4 * WSZ];   // [Wv, Wk, Wq, Wm] fp16
__device__ __align__(256) __half g_qh[(size_t)N_ * D_];   // [B,H,S,DK], pre-scaled 1/8
__device__ __align__(256) __half g_kh[(size_t)N_ * D_];
__device__ __align__(256) __half g_vh[(size_t)N_ * D_];
__device__ __align__(256) __half g_aoh[(size_t)N_ * D_];  // [B,S,D] fp16
__device__ unsigned g_mw[B_ * S_ * (S_ / 32)];

// ---------------- helpers ----------------------------------------------------------
__device__ __forceinline__ unsigned f2h2(float a, float b) {   // lo=a, hi=b
    unsigned r;
    asm("cvt.rn.f16x2.f32 %0, %1, %2;" : "=r"(r) : "f"(b), "f"(a));
    return r;
}
__device__ __forceinline__ uint2 cvt4h(float4 v) {
    return make_uint2(f2h2(v.x, v.y), f2h2(v.z, v.w));
}
__device__ __forceinline__ void mma16(float* c, const unsigned* a, const unsigned* b) {
    asm volatile(
        "mma.sync.aligned.m16n8k16.row.col.f32.f16.f16.f32 "
        "{%0,%1,%2,%3}, {%4,%5,%6,%7}, {%8,%9}, {%0,%1,%2,%3};"
        : "+f"(c[0]), "+f"(c[1]), "+f"(c[2]), "+f"(c[3])
        : "r"(a[0]), "r"(a[1]), "r"(a[2]), "r"(a[3]), "r"(b[0]), "r"(b[1]));
}
__device__ __forceinline__ void ldsm4(unsigned* r, unsigned addr) {
    asm volatile("ldmatrix.sync.aligned.m8n8.x4.shared.b16 {%0,%1,%2,%3}, [%4];"
                 : "=r"(r[0]), "=r"(r[1]), "=r"(r[2]), "=r"(r[3]) : "r"(addr));
}
__device__ __forceinline__ void ldsm4t(unsigned* r, unsigned addr) {
    asm volatile("ldmatrix.sync.aligned.m8n8.x4.trans.shared.b16 {%0,%1,%2,%3}, [%4];"
                 : "=r"(r[0]), "=r"(r[1]), "=r"(r[2]), "=r"(r[3]) : "r"(addr));
}
__device__ __forceinline__ void cp16(unsigned dst, const void* src) {
    asm volatile("cp.async.cg.shared.global [%0], [%1], 16;" :: "r"(dst), "l"(src));
}
__device__ __forceinline__ void cp_commit() { asm volatile("cp.async.commit_group;"); }
template <int NN>
__device__ __forceinline__ void cp_wait() {
    asm volatile("cp.async.wait_group %0;" :: "n"(NN));
}

// ---- K0: lora down for q and v in one launch (blockIdx.y selects stream) ---------
__global__ void lora_down_kernel(const float* __restrict__ xq, const float* __restrict__ xv,
                                 const float* __restrict__ Aqm, const float* __restrict__ Avm,
                                 float* __restrict__ outq, float* __restrict__ outv) {
    const float* x = blockIdx.y ? xv : xq;
    const float* A = blockIdx.y ? Avm : Aqm;
    float* out     = blockIdx.y ? outv : outq;
    int warp = (blockIdx.x * blockDim.x + threadIdx.x) >> 5;
    int lane = threadIdx.x & 31;
    float acc[8] = {0.f,0.f,0.f,0.f,0.f,0.f,0.f,0.f};
    const float* xr = x + (size_t)warp * D_;
    for (int k = lane; k < D_; k += 32) {
        float xval = xr[k];
        float4 a0 = *(const float4*)(A + k * 8);
        float4 a1 = *(const float4*)(A + k * 8 + 4);
        acc[0] += xval * a0.x; acc[1] += xval * a0.y; acc[2] += xval * a0.z; acc[3] += xval * a0.w;
        acc[4] += xval * a1.x; acc[5] += xval * a1.y; acc[6] += xval * a1.z; acc[7] += xval * a1.w;
    }
    #pragma unroll
    for (int r = 0; r < 8; r++) {
        #pragma unroll
        for (int off = 16; off > 0; off >>= 1)
            acc[r] += __shfl_xor_sync(0xffffffffu, acc[r], off);
    }
    if (lane == 0) {
        float4* o = (float4*)(out + (size_t)warp * 8);
        o[0] = make_float4(acc[0], acc[1], acc[2], acc[3]);
        o[1] = make_float4(acc[4], acc[5], acc[6], acc[7]);
    }
}

// ---- K1: lora up (q,v) + key cvt + W cvt, fused via blockIdx.y --------------------
__global__ void lora_up_kernel(const float* __restrict__ xq, const float* __restrict__ xv,
                               const float* __restrict__ key,
                               const float* __restrict__ Wv_, const float* __restrict__ Wk_,
                               const float* __restrict__ Wq_, const float* __restrict__ Wm_,
                               const float* __restrict__ Arq, const float* __restrict__ Arv,
                               const float* __restrict__ Bq, const float* __restrict__ Bv,
                               __half* __restrict__ oq, __half* __restrict__ ov,
                               __half* __restrict__ okey, __half* __restrict__ oW) {
    int i4 = blockIdx.x * blockDim.x + threadIdx.x;
    if (blockIdx.y == 3) {   // W matrices: pure convert, order [Wv, Wk, Wq, Wm]
        if (i4 >= 4 * WSZ / 4) return;
        int which = i4 / (WSZ / 4);
        size_t off = (size_t)(i4 - which * (WSZ / 4)) * 4;
        const float* src = which == 0 ? Wv_ : which == 1 ? Wk_ : which == 2 ? Wq_ : Wm_;
        *(uint2*)(oW + (size_t)which * WSZ + off) = cvt4h(*(const float4*)(src + off));
        return;
    }
    int row = i4 / (D_ / 4);
    int c = (i4 - row * (D_ / 4)) * 4;
    if (blockIdx.y == 2) {   // key: pure convert
        *(uint2*)(okey + (size_t)row * D_ + c) =
            cvt4h(*(const float4*)(key + (size_t)row * D_ + c));
        return;
    }
    const float* x  = blockIdx.y ? xv : xq;
    const float* Ar = blockIdx.y ? Arv : Arq;
    const float* Bm = blockIdx.y ? Bv : Bq;
    __half* out     = blockIdx.y ? ov : oq;
    float4 a0 = *(const float4*)(Ar + (size_t)row * 8);
    float4 a1 = *(const float4*)(Ar + (size_t)row * 8 + 4);
    float4 s = *(const float4*)(x + (size_t)row * D_ + c);
    #pragma unroll
    for (int k = 0; k < 8; k++) {
        float a = k == 0 ? a0.x : k == 1 ? a0.y : k == 2 ? a0.z : k == 3 ? a0.w
                : k == 4 ? a1.x : k == 5 ? a1.y : k == 6 ? a1.z : a1.w;
        float4 bm = *(const float4*)(Bm + k * D_ + c);
        s.x += a * bm.x; s.y += a * bm.y; s.z += a * bm.z; s.w += a * bm.w;
    }
    *(uint2*)(out + (size_t)row * D_ + c) = cvt4h(s);
}

// -------- K1b: pack mask ints into bits ---------------------------------------------
__global__ void mask_pack_kernel(const int* __restrict__ mask,
                                 unsigned* __restrict__ mw) {
    int w = blockIdx.x * blockDim.x + threadIdx.x;
    const int4* mp = (const int4*)(mask + (size_t)w * 32);
    unsigned bits = 0;
    #pragma unroll
    for (int j = 0; j < 8; j++) {
        int4 v = mp[j];
        bits |= (v.x != 0 ? 1u : 0u) << (j * 4 + 0);
        bits |= (v.y != 0 ? 1u : 0u) << (j * 4 + 1);
        bits |= (v.z != 0 ? 1u : 0u) << (j * 4 + 2);
        bits |= (v.w != 0 ? 1u : 0u) << (j * 4 + 3);
    }
    mw[w] = bits;
}

// ---- GEMM body: all-fp16 inputs, BM=128, BN=128, BK=32 (unchanged from R12) -------
#define GSTW 20   // words per 32-half row; row stride 80B
__device__ __forceinline__ void gemm_body(
    const __half* __restrict__ A, const __half* __restrict__ W,
    const float* __restrict__ bias, void* __restrict__ Cv,
    float scale, int headPermute, int bx, int by,
    unsigned* As, unsigned* Bs) {

    int tid = threadIdx.x;
    int warp = tid >> 5, lane = tid & 31;
    int wm = warp & 1, wn = warp >> 1;
    int lr = lane >> 2, lc = lane & 3;
    int i0 = bx * 128, n0 = by * 128;

    int mIdx = lane >> 3, l7 = lane & 7;
    int rowA = ((mIdx & 1) << 3) + l7, colA = (mIdx >> 1) << 4;
    int rowB = ((mIdx >> 1) << 3) + l7, colB = (mIdx & 1) << 4;
    unsigned asB = (unsigned)__cvta_generic_to_shared(As);
    unsigned bsB = (unsigned)__cvta_generic_to_shared(Bs);

    int arow = tid >> 1, aseg = (tid & 1) << 4;
    const __half* Ap = A + (size_t)(i0 + arow) * D_ + aseg;
    const __half* Wp = W + (size_t)(n0 + arow) * D_ + aseg;
    int akw = aseg >> 1;

    float c[4][4][4];
    #pragma unroll
    for (int mi = 0; mi < 4; mi++)
        #pragma unroll
        for (int ni = 0; ni < 4; ni++)
            #pragma unroll
            for (int q = 0; q < 4; q++) c[mi][ni][q] = 0.f;

    uint4 rah[2], rbh[2];
    rah[0] = *(const uint4*)Ap;       rah[1] = *(const uint4*)(Ap + 8);
    rbh[0] = *(const uint4*)Wp;       rbh[1] = *(const uint4*)(Wp + 8);
    *(uint4*)&As[arow * GSTW + akw] = rah[0];
    *(uint4*)&As[arow * GSTW + akw + 4] = rah[1];
    *(uint4*)&Bs[arow * GSTW + akw] = rbh[0];
    *(uint4*)&Bs[arow * GSTW + akw + 4] = rbh[1];
    __syncthreads();

    for (int it = 0; it < 24; it++) {
        int buf = it & 1;
        if (it < 23) {
            int k0 = (it + 1) * 32;
            rah[0] = *(const uint4*)(Ap + k0);  rah[1] = *(const uint4*)(Ap + k0 + 8);
            rbh[0] = *(const uint4*)(Wp + k0);  rbh[1] = *(const uint4*)(Wp + k0 + 8);
        }

        #pragma unroll
        for (int t = 0; t < 2; t++) {
            unsigned af[4][4], bb[2][4];
            #pragma unroll
            for (int mi = 0; mi < 4; mi++)
                ldsm4(af[mi], asB + (unsigned)((buf * 128 + wm * 64 + mi * 16 + rowA) * 80 + t * 32 + colA));
            #pragma unroll
            for (int np = 0; np < 2; np++)
                ldsm4(bb[np], bsB + (unsigned)((buf * 128 + wn * 32 + np * 16 + rowB) * 80 + t * 32 + colB));
            #pragma unroll
            for (int mi = 0; mi < 4; mi++)
                #pragma unroll
                for (int np = 0; np < 2; np++) {
                    mma16(c[mi][2 * np],     af[mi], &bb[np][0]);
                    mma16(c[mi][2 * np + 1], af[mi], &bb[np][2]);
                }
        }

        if (it < 23) {
            int nb = buf ^ 1;
            *(uint4*)&As[(nb * 128 + arow) * GSTW + akw] = rah[0];
            *(uint4*)&As[(nb * 128 + arow) * GSTW + akw + 4] = rah[1];
            *(uint4*)&Bs[(nb * 128 + arow) * GSTW + akw] = rbh[0];
            *(uint4*)&Bs[(nb * 128 + arow) * GSTW + akw + 4] = rbh[1];
        }
        __syncthreads();
    }

    #pragma unroll
    for (int mi = 0; mi < 4; mi++) {
        #pragma unroll
        for (int ni = 0; ni < 4; ni++) {
            int i = i0 + wm * 64 + mi * 16 + lr;
            int j = n0 + wn * 32 + ni * 8 + 2 * lc;
            float b0 = bias[j], b1 = bias[j + 1];
            float v00 = scale * (c[mi][ni][0] + b0), v01 = scale * (c[mi][ni][1] + b1);
            float v10 = scale * (c[mi][ni][2] + b0), v11 = scale * (c[mi][ni][3] + b1);
            if (headPermute) {
                __half* Ch = (__half*)Cv;
                int bb2 = i >> 11, s = i & 2047;
                int hh = j >> 6, dk = j & 63;
                *(unsigned*)(Ch + (((size_t)(bb2 * H_ + hh)) * S_ + s) * DK_ + dk) = f2h2(v00, v01);
                *(unsigned*)(Ch + (((size_t)(bb2 * H_ + hh)) * S_ + (s + 8)) * DK_ + dk) = f2h2(v10, v11);
            } else {
                float* Cf = (float*)Cv;
                *(float2*)(Cf + (size_t)i * D_ + j) = make_float2(v00, v01);
                *(float2*)(Cf + (size_t)(i + 8) * D_ + j) = make_float2(v10, v11);
            }
        }
    }
}

struct Gemm3Args {
    const __half* A[3];
    const __half* W[3];
    const float*  bias[3];
    __half*       C[3];
    float         scale[3];
};
__global__ void __launch_bounds__(256, 2)
gemm3_kernel(Gemm3Args args) {
    __shared__ unsigned As[2 * 128 * GSTW];
    __shared__ unsigned Bs[2 * 128 * GSTW];
    int z = blockIdx.z;
    gemm_body(args.A[z], args.W[z], args.bias[z], args.C[z], args.scale[z], 1,
              blockIdx.x, blockIdx.y, As, Bs);
}

__global__ void __launch_bounds__(256, 2)
gemm1_kernel(const __half* __restrict__ A, const __half* __restrict__ W,
             const float* __restrict__ bias, float* __restrict__ C) {
    __shared__ unsigned As[2 * 128 * GSTW];
    __shared__ unsigned Bs[2 * 128 * GSTW];
    gemm_body(A, W, bias, C, 1.0f, 0, blockIdx.x, blockIdx.y, As, Bs);
}

// ---------------- K3: flash attention — 4 warps, strip 32, shared B-frags ----------
// 128 threads; each warp owns 32 q rows = 2 m-tiles sharing every K/V fragment.
#define ASTW 36
#define ATTN_SMEM (4 * 64 * ASTW * 4)
__global__ void __launch_bounds__(128, 2)
attn_h_kernel(const unsigned* __restrict__ mw, __half* __restrict__ out) {
    extern __shared__ unsigned sm[];
    unsigned* Ks = sm;
    unsigned* Vs = sm + 2 * 64 * ASTW;

    int tid = threadIdx.x, warp = tid >> 5, lane = tid & 31;
    int lr = lane >> 2, lc = lane & 3;
    int rb = warp * 32;
    int qb = blockIdx.x, h = blockIdx.y, b = blockIdx.z;
    int q0 = qb * 128, bh = b * H_ + h;

    const __half* qg = g_qh + ((size_t)bh * S_ + q0) * DK_;
    const __half* kg = g_kh + (size_t)bh * S_ * DK_;
    const __half* vg = g_vh + (size_t)bh * S_ * DK_;

    int mIdx = lane >> 3, l7 = lane & 7;
    int rowK = ((mIdx >> 1) << 3) + l7, colK = (mIdx & 1) << 4;
    int rowV = ((mIdx & 1) << 3) + l7, colV = (mIdx >> 1) << 4;
    unsigned ksB = (unsigned)__cvta_generic_to_shared(Ks);
    unsigned vsB = (unsigned)__cvta_generic_to_shared(Vs);

    // Q fragments: 2 m-tiles per warp
    unsigned qf[2][4][4];
    #pragma unroll
    for (int mi = 0; mi < 2; mi++) {
        const unsigned* u0 = (const unsigned*)(qg + (size_t)(rb + mi * 16 + lr) * DK_);
        const unsigned* u1 = (const unsigned*)(qg + (size_t)(rb + mi * 16 + lr + 8) * DK_);
        #pragma unroll
        for (int t = 0; t < 4; t++) {
            qf[mi][t][0] = u0[8 * t + lc];
            qf[mi][t][1] = u1[8 * t + lc];
            qf[mi][t][2] = u0[8 * t + 4 + lc];
            qf[mi][t][3] = u1[8 * t + 4 + lc];
        }
    }

    // cp.async fill: 512 chunks per tensor, 128 threads -> 4 chunks each
    #pragma unroll
    for (int p = 0; p < 4; p++) {
        int rc = tid + p * 128;
        int row = rc >> 3, cc = (rc & 7) << 3;
        cp16(ksB + (unsigned)(row * 144 + cc * 2), kg + (size_t)row * DK_ + cc);
        cp16(vsB + (unsigned)(row * 144 + cc * 2), vg + (size_t)row * DK_ + cc);
    }
    cp_commit();

    float o[2][8][4];
    float m[2][2], l[2][2];
    #pragma unroll
    for (int mi = 0; mi < 2; mi++) {
        m[mi][0] = -1e30f; m[mi][1] = -1e30f;
        l[mi][0] = 0.f;    l[mi][1] = 0.f;
        #pragma unroll
        for (int ni = 0; ni < 8; ni++)
            #pragma unroll
            for (int q = 0; q < 4; q++) o[mi][ni][q] = 0.f;
    }

    for (int kb = 0; kb < S_ / 64; kb++) {
        int buf = kb & 1;
        if (kb + 1 < S_ / 64) {
            int nb = buf ^ 1;
            size_t k0n = (size_t)(kb + 1) * 64;
            #pragma unroll
            for (int p = 0; p < 4; p++) {
                int rc = tid + p * 128;
                int row = rc >> 3, cc = (rc & 7) << 3;
                cp16(ksB + (unsigned)((nb * 64 + row) * 144 + cc * 2), kg + (k0n + row) * DK_ + cc);
                cp16(vsB + (unsigned)((nb * 64 + row) * 144 + cc * 2), vg + (k0n + row) * DK_ + cc);
            }
            cp_commit();
            cp_wait<1>();
        } else {
            cp_wait<0>();
        }
        __syncthreads();

        unsigned kbase = ksB + (unsigned)(buf * 64) * 144;
        unsigned vbase = vsB + (unsigned)(buf * 64) * 144;

        // --- S = Q K^T : B-frags shared across both m-tiles ---
        float s[2][8][4];
        #pragma unroll
        for (int mi = 0; mi < 2; mi++)
            #pragma unroll
            for (int ni = 0; ni < 8; ni++)
                #pragma unroll
                for (int q = 0; q < 4; q++) s[mi][ni][q] = 0.f;

        #pragma unroll
        for (int t = 0; t < 4; t++) {
            #pragma unroll
            for (int np = 0; np < 4; np++) {
                unsigned bf[4];
                ldsm4(bf, kbase + (unsigned)((np * 16 + rowK) * 144 + t * 32 + colK));
                #pragma unroll
                for (int mi = 0; mi < 2; mi++) {
                    mma16(s[mi][2 * np],     qf[mi][t], &bf[0]);
                    mma16(s[mi][2 * np + 1], qf[mi][t], &bf[2]);
                }
            }
        }

        // --- mask + online softmax (registers only) ---
        #pragma unroll
        for (int mi = 0; mi < 2; mi++) {
            #pragma unroll
            for (int hh = 0; hh < 2; hh++) {
                int grow = q0 + rb + mi * 16 + hh * 8 + lr;
                uint2 w = *(const uint2*)(mw + ((size_t)b * S_ + grow) * (S_ / 32) + kb * 2);
                float rmax = -1e30f;
                #pragma unroll
                for (int ni = 0; ni < 8; ni++) {
                    int col = ni * 8 + 2 * lc;
                    unsigned ws = (col < 32) ? w.x : w.y;
                    int bit = col & 31;
                    float* sp = &s[mi][ni][hh * 2];
                    if (!((ws >> bit) & 1u))       sp[0] = -1e9f;
                    if (!((ws >> (bit + 1)) & 1u)) sp[1] = -1e9f;
                    rmax = fmaxf(rmax, fmaxf(sp[0], sp[1]));
                }
                rmax = fmaxf(rmax, __shfl_xor_sync(0xffffffffu, rmax, 1));
                rmax = fmaxf(rmax, __shfl_xor_sync(0xffffffffu, rmax, 2));
                float mn = fmaxf(m[mi][hh], rmax);
                float corr = __expf(m[mi][hh] - mn);
                m[mi][hh] = mn;
                float rs = 0.f;
                #pragma unroll
                for (int ni = 0; ni < 8; ni++) {
                    float* sp = &s[mi][ni][hh * 2];
                    float p0 = __expf(sp[0] - mn);
                    float p1 = __expf(sp[1] - mn);
                    rs += p0 + p1;
                    sp[0] = p0; sp[1] = p1;
                    o[mi][ni][hh * 2]     *= corr;
                    o[mi][ni][hh * 2 + 1] *= corr;
                }
                rs += __shfl_xor_sync(0xffffffffu, rs, 1);
                rs += __shfl_xor_sync(0xffffffffu, rs, 2);
                l[mi][hh] = l[mi][hh] * corr + rs;
            }
        }

        // --- O += P @ V : V-frags shared across both m-tiles ---
        #pragma unroll
        for (int t = 0; t < 4; t++) {
            unsigned a[2][4];
            #pragma unroll
            for (int mi = 0; mi < 2; mi++) {
                a[mi][0] = f2h2(s[mi][2 * t][0],     s[mi][2 * t][1]);
                a[mi][1] = f2h2(s[mi][2 * t][2],     s[mi][2 * t][3]);
                a[mi][2] = f2h2(s[mi][2 * t + 1][0], s[mi][2 * t + 1][1]);
                a[mi][3] = f2h2(s[mi][2 * t + 1][2], s[mi][2 * t + 1][3]);
            }
            #pragma unroll
            for (int np = 0; np < 4; np++) {
                unsigned bf[4];
                ldsm4t(bf, vbase + (unsigned)((t * 16 + rowV) * 144 + np * 32 + colV));
                #pragma unroll
                for (int mi = 0; mi < 2; mi++) {
                    mma16(o[mi][2 * np],     a[mi], &bf[0]);
                    mma16(o[mi][2 * np + 1], a[mi], &bf[2]);
                }
            }
        }
        __syncthreads();
    }

    // --- epilogue: O / l -> fp16 out ---
    #pragma unroll
    for (int mi = 0; mi < 2; mi++) {
        #pragma unroll
        for (int hh = 0; hh < 2; hh++) {
            float inv = 1.0f / l[mi][hh];
            int grow = q0 + rb + mi * 16 + hh * 8 + lr;
            #pragma unroll
            for (int ni = 0; ni < 8; ni++) {
                int col = ni * 8 + 2 * lc;
                *(unsigned*)(out + ((size_t)(b * S_ + grow)) * D_ + h * DK_ + col) =
                    f2h2(o[mi][ni][hh * 2] * inv, o[mi][ni][hh * 2 + 1] * inv);
            }
        }
    }
}

// --------------------------------- host ---------------------------------------------
extern "C" void kernel_launch(void* const* d_in, const int* in_sizes, int n_in,
                              void* d_out, int out_size) {
    const float* query = (const float*)d_in[0];
    const float* key   = (const float*)d_in[1];
    const float* value = (const float*)d_in[2];
    const int*   mask  = (const int*)d_in[3];
    const float* lAq   = (const float*)d_in[4];
    const float* lBq   = (const float*)d_in[5];
    const float* lAv   = (const float*)d_in[6];
    const float* lBv   = (const float*)d_in[7];
    const float* Wq    = (const float*)d_in[8];
    const float* bq    = (const float*)d_in[9];
    const float* Wk    = (const float*)d_in[10];
    const float* bk    = (const float*)d_in[11];
    const float* Wv    = (const float*)d_in[12];
    const float* bv    = (const float*)d_in[13];
    const float* Wm    = (const float*)d_in[14];
    const float* bm    = (const float*)d_in[15];

    void *pAq, *pAv, *pQadjh, *pVadjh, *pkeyh, *pWh, *pqh, *pkh, *pvh, *paoh, *pmw;
    cudaGetSymbolAddress(&pAq,    g_Aq);
    cudaGetSymbolAddress(&pAv,    g_Av);
    cudaGetSymbolAddress(&pQadjh, g_Qadjh);
    cudaGetSymbolAddress(&pVadjh, g_Vadjh);
    cudaGetSymbolAddress(&pkeyh,  g_keyh);
    cudaGetSymbolAddress(&pWh,    g_Wh);
    cudaGetSymbolAddress(&pqh,    g_qh);
    cudaGetSymbolAddress(&pkh,    g_kh);
    cudaGetSymbolAddress(&pvh,    g_vh);
    cudaGetSymbolAddress(&paoh,   g_aoh);
    cudaGetSymbolAddress(&pmw,    g_mw);

    const __half* Whv = (const __half*)pWh;
    const __half* Whk = Whv + WSZ;
    const __half* Whq = Whv + 2 * WSZ;
    const __half* Whm = Whv + 3 * WSZ;

    // mask pack (independent)
    mask_pack_kernel<<<(B_ * S_ * (S_ / 32)) / 256, 256>>>(mask, (unsigned*)pmw);

    // LoRA down (q and v fused)
    lora_down_kernel<<<dim3(N_ / 8, 2), 256>>>(query, value, lAq, lAv,
                                               (float*)pAq, (float*)pAv);

    // LoRA up (q,v) + key cvt + W cvt, one launch
    lora_up_kernel<<<dim3(N_ * D_ / 4 / 256, 4), 256>>>(
        query, value, key, Wv, Wk, Wq, Wm,
        (const float*)pAq, (const float*)pAv, lBq, lBv,
        (__half*)pQadjh, (__half*)pVadjh, (__half*)pkeyh, (__half*)pWh);

    // Fused projections (reference's stream swap preserved)
    Gemm3Args ga;
    ga.A[0] = (const __half*)pQadjh; ga.W[0] = Whv; ga.bias[0] = bv; ga.C[0] = (__half*)pvh; ga.scale[0] = 1.0f;
    ga.A[1] = (const __half*)pkeyh;  ga.W[1] = Whk; ga.bias[1] = bk; ga.C[1] = (__half*)pkh; ga.scale[1] = 1.0f;
    ga.A[2] = (const __half*)pVadjh; ga.W[2] = Whq; ga.bias[2] = bq; ga.C[2] = (__half*)pqh; ga.scale[2] = 0.125f;
    gemm3_kernel<<<dim3(N_ / 128, D_ / 128, 3), 256>>>(ga);

    // Flash attention -> fp16 ao (4 warps, strip 32)
    cudaFuncSetAttribute(attn_h_kernel, cudaFuncAttributeMaxDynamicSharedMemorySize, ATTN_SMEM);
    attn_h_kernel<<<dim3(S_ / 128, H_, B_), 128, ATTN_SMEM>>>((const unsigned*)pmw, (__half*)paoh);

    // Final: out = ao @ Wm^T + bm (fp32 out)
    gemm1_kernel<<<dim3(N_ / 128, D_ / 128), 256>>>((const __half*)paoh, Whm, bm, (float*)d_out);
}

// round 14
// speedup vs baseline: 1.0081x; 1.0081x over previous
#include <cuda_runtime.h>
#include <cuda_fp16.h>
#include <cstdint>

#define B_ 2
#define S_ 2048
#define D_ 768
#define H_ 12
#define DK_ 64
#define R_ 8
#define N_ 4096   // B_*S_
#define WSZ (D_ * D_)

// ---------------- scratch (static device globals; no allocation) ----------------
__device__ float  g_Aq[N_ * R_];
__device__ float  g_Av[N_ * R_];
__device__ __align__(256) __half g_Qadjh[(size_t)N_ * D_];
__device__ __align__(256) __half g_Vadjh[(size_t)N_ * D_];
__device__ __align__(256) __half g_keyh[(size_t)N_ * D_];
__device__ __align__(256) __half g_Wh[(size_t)4 * WSZ];   // [Wv, Wk, Wq, Wm] fp16
__device__ __align__(256) __half g_qh[(size_t)N_ * D_];   // [B,H,S,DK], pre-scaled 1/8
__device__ __align__(256) __half g_kh[(size_t)N_ * D_];
__device__ __align__(256) __half g_vh[(size_t)N_ * D_];
__device__ __align__(256) __half g_aoh[(size_t)N_ * D_];  // [B,S,D] fp16
__device__ unsigned g_mw[B_ * S_ * (S_ / 32)];

// ---------------- helpers ----------------------------------------------------------
__device__ __forceinline__ unsigned f2h2(float a, float b) {   // lo=a, hi=b
    unsigned r;
    asm("cvt.rn.f16x2.f32 %0, %1, %2;" : "=r"(r) : "f"(b), "f"(a));
    return r;
}
__device__ __forceinline__ uint2 cvt4h(float4 v) {
    return make_uint2(f2h2(v.x, v.y), f2h2(v.z, v.w));
}
__device__ __forceinline__ void mma16(float* c, const unsigned* a, const unsigned* b) {
    asm volatile(
        "mma.sync.aligned.m16n8k16.row.col.f32.f16.f16.f32 "
        "{%0,%1,%2,%3}, {%4,%5,%6,%7}, {%8,%9}, {%0,%1,%2,%3};"
        : "+f"(c[0]), "+f"(c[1]), "+f"(c[2]), "+f"(c[3])
        : "r"(a[0]), "r"(a[1]), "r"(a[2]), "r"(a[3]), "r"(b[0]), "r"(b[1]));
}
__device__ __forceinline__ void ldsm4(unsigned* r, unsigned addr) {
    asm volatile("ldmatrix.sync.aligned.m8n8.x4.shared.b16 {%0,%1,%2,%3}, [%4];"
                 : "=r"(r[0]), "=r"(r[1]), "=r"(r[2]), "=r"(r[3]) : "r"(addr));
}
__device__ __forceinline__ void ldsm4t(unsigned* r, unsigned addr) {
    asm volatile("ldmatrix.sync.aligned.m8n8.x4.trans.shared.b16 {%0,%1,%2,%3}, [%4];"
                 : "=r"(r[0]), "=r"(r[1]), "=r"(r[2]), "=r"(r[3]) : "r"(addr));
}
__device__ __forceinline__ void cp16(unsigned dst, const void* src) {
    asm volatile("cp.async.cg.shared.global [%0], [%1], 16;" :: "r"(dst), "l"(src));
}
__device__ __forceinline__ void cp_commit() { asm volatile("cp.async.commit_group;"); }
template <int NN>
__device__ __forceinline__ void cp_wait() {
    asm volatile("cp.async.wait_group %0;" :: "n"(NN));
}

// ---- K0: lora down for q and v in one launch (blockIdx.y selects stream) ---------
__global__ void lora_down_kernel(const float* __restrict__ xq, const float* __restrict__ xv,
                                 const float* __restrict__ Aqm, const float* __restrict__ Avm,
                                 float* __restrict__ outq, float* __restrict__ outv) {
    const float* x = blockIdx.y ? xv : xq;
    const float* A = blockIdx.y ? Avm : Aqm;
    float* out     = blockIdx.y ? outv : outq;
    int warp = (blockIdx.x * blockDim.x + threadIdx.x) >> 5;
    int lane = threadIdx.x & 31;
    float acc[8] = {0.f,0.f,0.f,0.f,0.f,0.f,0.f,0.f};
    const float* xr = x + (size_t)warp * D_;
    for (int k = lane; k < D_; k += 32) {
        float xval = xr[k];
        float4 a0 = *(const float4*)(A + k * 8);
        float4 a1 = *(const float4*)(A + k * 8 + 4);
        acc[0] += xval * a0.x; acc[1] += xval * a0.y; acc[2] += xval * a0.z; acc[3] += xval * a0.w;
        acc[4] += xval * a1.x; acc[5] += xval * a1.y; acc[6] += xval * a1.z; acc[7] += xval * a1.w;
    }
    #pragma unroll
    for (int r = 0; r < 8; r++) {
        #pragma unroll
        for (int off = 16; off > 0; off >>= 1)
            acc[r] += __shfl_xor_sync(0xffffffffu, acc[r], off);
    }
    if (lane == 0) {
        float4* o = (float4*)(out + (size_t)warp * 8);
        o[0] = make_float4(acc[0], acc[1], acc[2], acc[3]);
        o[1] = make_float4(acc[4], acc[5], acc[6], acc[7]);
    }
}

// ---- K1: lora up (q,v) + key cvt + W cvt, fused via blockIdx.y --------------------
__global__ void lora_up_kernel(const float* __restrict__ xq, const float* __restrict__ xv,
                               const float* __restrict__ key,
                               const float* __restrict__ Wv_, const float* __restrict__ Wk_,
                               const float* __restrict__ Wq_, const float* __restrict__ Wm_,
                               const float* __restrict__ Arq, const float* __restrict__ Arv,
                               const float* __restrict__ Bq, const float* __restrict__ Bv,
                               __half* __restrict__ oq, __half* __restrict__ ov,
                               __half* __restrict__ okey, __half* __restrict__ oW) {
    int i4 = blockIdx.x * blockDim.x + threadIdx.x;
    if (blockIdx.y == 3) {   // W matrices: pure convert, order [Wv, Wk, Wq, Wm]
        if (i4 >= 4 * WSZ / 4) return;
        int which = i4 / (WSZ / 4);
        size_t off = (size_t)(i4 - which * (WSZ / 4)) * 4;
        const float* src = which == 0 ? Wv_ : which == 1 ? Wk_ : which == 2 ? Wq_ : Wm_;
        *(uint2*)(oW + (size_t)which * WSZ + off) = cvt4h(*(const float4*)(src + off));
        return;
    }
    int row = i4 / (D_ / 4);
    int c = (i4 - row * (D_ / 4)) * 4;
    if (blockIdx.y == 2) {   // key: pure convert
        *(uint2*)(okey + (size_t)row * D_ + c) =
            cvt4h(*(const float4*)(key + (size_t)row * D_ + c));
        return;
    }
    const float* x  = blockIdx.y ? xv : xq;
    const float* Ar = blockIdx.y ? Arv : Arq;
    const float* Bm = blockIdx.y ? Bv : Bq;
    __half* out     = blockIdx.y ? ov : oq;
    float4 a0 = *(const float4*)(Ar + (size_t)row * 8);
    float4 a1 = *(const float4*)(Ar + (size_t)row * 8 + 4);
    float4 s = *(const float4*)(x + (size_t)row * D_ + c);
    #pragma unroll
    for (int k = 0; k < 8; k++) {
        float a = k == 0 ? a0.x : k == 1 ? a0.y : k == 2 ? a0.z : k == 3 ? a0.w
                : k == 4 ? a1.x : k == 5 ? a1.y : k == 6 ? a1.z : a1.w;
        float4 bm = *(const float4*)(Bm + k * D_ + c);
        s.x += a * bm.x; s.y += a * bm.y; s.z += a * bm.z; s.w += a * bm.w;
    }
    *(uint2*)(out + (size_t)row * D_ + c) = cvt4h(s);
}

// -------- K1b: pack mask ints into bits ---------------------------------------------
__global__ void mask_pack_kernel(const int* __restrict__ mask,
                                 unsigned* __restrict__ mw) {
    int w = blockIdx.x * blockDim.x + threadIdx.x;
    const int4* mp = (const int4*)(mask + (size_t)w * 32);
    unsigned bits = 0;
    #pragma unroll
    for (int j = 0; j < 8; j++) {
        int4 v = mp[j];
        bits |= (v.x != 0 ? 1u : 0u) << (j * 4 + 0);
        bits |= (v.y != 0 ? 1u : 0u) << (j * 4 + 1);
        bits |= (v.z != 0 ? 1u : 0u) << (j * 4 + 2);
        bits |= (v.w != 0 ? 1u : 0u) << (j * 4 + 3);
    }
    mw[w] = bits;
}

// ---- GEMM body: all-fp16, BM=128, BN=256, BK=32; 8 warps 2m x 4n, warp 64x64 -----
#define GSTW 20   // words per 32-half row; row stride 80B
#define GEMM_SMEM ((2 * 128 + 2 * 256) * GSTW * 4)   // 61440 B dynamic
__device__ __forceinline__ void gemm_body(
    const __half* __restrict__ A, const __half* __restrict__ W,
    const float* __restrict__ bias, void* __restrict__ Cv,
    float scale, int headPermute, int bx, int by,
    unsigned* As, unsigned* Bs) {

    int tid = threadIdx.x;
    int warp = tid >> 5, lane = tid & 31;
    int wm = warp & 1, wn = warp >> 1;
    int lr = lane >> 2, lc = lane & 3;
    int i0 = bx * 128, n0 = by * 256;

    int mIdx = lane >> 3, l7 = lane & 7;
    int rowA = ((mIdx & 1) << 3) + l7, colA = (mIdx >> 1) << 4;
    int rowB = ((mIdx >> 1) << 3) + l7, colB = (mIdx & 1) << 4;
    unsigned asB = (unsigned)__cvta_generic_to_shared(As);
    unsigned bsB = (unsigned)__cvta_generic_to_shared(Bs);

    // A: 128 rows x 32 halves -> each thread one 16-half seg
    int arow = tid >> 1, aseg = (tid & 1) << 4;
    const __half* Ap = A + (size_t)(i0 + arow) * D_ + aseg;
    int akw = aseg >> 1;
    // B: 256 rows x 32 halves -> each thread one full row
    const __half* Wp = W + (size_t)(n0 + tid) * D_;

    float c[4][8][4];
    #pragma unroll
    for (int mi = 0; mi < 4; mi++)
        #pragma unroll
        for (int nj = 0; nj < 8; nj++)
            #pragma unroll
            for (int q = 0; q < 4; q++) c[mi][nj][q] = 0.f;

    uint4 rah[2], rbh[4];
    rah[0] = *(const uint4*)Ap;        rah[1] = *(const uint4*)(Ap + 8);
    #pragma unroll
    for (int p = 0; p < 4; p++) rbh[p] = *(const uint4*)(Wp + 8 * p);
    *(uint4*)&As[arow * GSTW + akw] = rah[0];
    *(uint4*)&As[arow * GSTW + akw + 4] = rah[1];
    #pragma unroll
    for (int p = 0; p < 4; p++) *(uint4*)&Bs[tid * GSTW + 4 * p] = rbh[p];
    __syncthreads();

    for (int it = 0; it < 24; it++) {
        int buf = it & 1;
        if (it < 23) {
            int k0 = (it + 1) * 32;
            rah[0] = *(const uint4*)(Ap + k0);  rah[1] = *(const uint4*)(Ap + k0 + 8);
            #pragma unroll
            for (int p = 0; p < 4; p++) rbh[p] = *(const uint4*)(Wp + k0 + 8 * p);
        }

        #pragma unroll
        for (int t = 0; t < 2; t++) {
            unsigned af[4][4], bb[4][4];
            #pragma unroll
            for (int mi = 0; mi < 4; mi++)
                ldsm4(af[mi], asB + (unsigned)((buf * 128 + wm * 64 + mi * 16 + rowA) * 80 + t * 32 + colA));
            #pragma unroll
            for (int np = 0; np < 4; np++)
                ldsm4(bb[np], bsB + (unsigned)((buf * 256 + wn * 64 + np * 16 + rowB) * 80 + t * 32 + colB));
            #pragma unroll
            for (int mi = 0; mi < 4; mi++)
                #pragma unroll
                for (int np = 0; np < 4; np++) {
                    mma16(c[mi][2 * np],     af[mi], &bb[np][0]);
                    mma16(c[mi][2 * np + 1], af[mi], &bb[np][2]);
                }
        }

        if (it < 23) {
            int nb = buf ^ 1;
            *(uint4*)&As[(nb * 128 + arow) * GSTW + akw] = rah[0];
            *(uint4*)&As[(nb * 128 + arow) * GSTW + akw + 4] = rah[1];
            #pragma unroll
            for (int p = 0; p < 4; p++)
                *(uint4*)&Bs[(nb * 256 + tid) * GSTW + 4 * p] = rbh[p];
        }
        __syncthreads();
    }

    #pragma unroll
    for (int mi = 0; mi < 4; mi++) {
        #pragma unroll
        for (int nj = 0; nj < 8; nj++) {
            int i = i0 + wm * 64 + mi * 16 + lr;
            int j = n0 + wn * 64 + nj * 8 + 2 * lc;
            float b0 = bias[j], b1 = bias[j + 1];
            float v00 = scale * (c[mi][nj][0] + b0), v01 = scale * (c[mi][nj][1] + b1);
            float v10 = scale * (c[mi][nj][2] + b0), v11 = scale * (c[mi][nj][3] + b1);
            if (headPermute) {
                __half* Ch = (__half*)Cv;
                int bb2 = i >> 11, s = i & 2047;
                int hh = j >> 6, dk = j & 63;
                *(unsigned*)(Ch + (((size_t)(bb2 * H_ + hh)) * S_ + s) * DK_ + dk) = f2h2(v00, v01);
                *(unsigned*)(Ch + (((size_t)(bb2 * H_ + hh)) * S_ + (s + 8)) * DK_ + dk) = f2h2(v10, v11);
            } else {
                float* Cf = (float*)Cv;
                *(float2*)(Cf + (size_t)i * D_ + j) = make_float2(v00, v01);
                *(float2*)(Cf + (size_t)(i + 8) * D_ + j) = make_float2(v10, v11);
            }
        }
    }
}

struct Gemm3Args {
    const __half* A[3];
    const __half* W[3];
    const float*  bias[3];
    __half*       C[3];
    float         scale[3];
};
__global__ void __launch_bounds__(256, 1)
gemm3_kernel(Gemm3Args args) {
    extern __shared__ unsigned gsm[];
    unsigned* As = gsm;
    unsigned* Bs = gsm + 2 * 128 * GSTW;
    int z = blockIdx.z;
    gemm_body(args.A[z], args.W[z], args.bias[z], args.C[z], args.scale[z], 1,
              blockIdx.x, blockIdx.y, As, Bs);
}

__global__ void __launch_bounds__(256, 1)
gemm1_kernel(const __half* __restrict__ A, const __half* __restrict__ W,
             const float* __restrict__ bias, float* __restrict__ C) {
    extern __shared__ unsigned gsm[];
    unsigned* As = gsm;
    unsigned* Bs = gsm + 2 * 128 * GSTW;
    gemm_body(A, W, bias, C, 1.0f, 0, blockIdx.x, blockIdx.y, As, Bs);
}

// ---------------- K3: flash attention — R12 version (8 warps, strip 16) ------------
#define ASTW 36
#define ATTN_SMEM (4 * 64 * ASTW * 4)
__global__ void __launch_bounds__(256, 2)
attn_h_kernel(const unsigned* __restrict__ mw, __half* __restrict__ out) {
    extern __shared__ unsigned sm[];
    unsigned* Ks = sm;
    unsigned* Vs = sm + 2 * 64 * ASTW;

    int tid = threadIdx.x, warp = tid >> 5, lane = tid & 31;
    int lr = lane >> 2, lc = lane & 3;
    int rb = warp * 16;
    int qb = blockIdx.x, h = blockIdx.y, b = blockIdx.z;
    int q0 = qb * 128, bh = b * H_ + h;

    const __half* qg = g_qh + ((size_t)bh * S_ + q0) * DK_;
    const __half* kg = g_kh + (size_t)bh * S_ * DK_;
    const __half* vg = g_vh + (size_t)bh * S_ * DK_;

    int mIdx = lane >> 3, l7 = lane & 7;
    int rowK = ((mIdx >> 1) << 3) + l7, colK = (mIdx & 1) << 4;
    int rowV = ((mIdx & 1) << 3) + l7, colV = (mIdx >> 1) << 4;
    unsigned ksB = (unsigned)__cvta_generic_to_shared(Ks);
    unsigned vsB = (unsigned)__cvta_generic_to_shared(Vs);

    int r0c = tid >> 3, c0c = (tid & 7) << 3;
    int r1c = (tid + 256) >> 3, c1c = c0c;

    unsigned qf[4][4];
    {
        const unsigned* u0 = (const unsigned*)(qg + (size_t)(rb + lr) * DK_);
        const unsigned* u1 = (const unsigned*)(qg + (size_t)(rb + lr + 8) * DK_);
        #pragma unroll
        for (int t = 0; t < 4; t++) {
            qf[t][0] = u0[8 * t + lc];
            qf[t][1] = u1[8 * t + lc];
            qf[t][2] = u0[8 * t + 4 + lc];
            qf[t][3] = u1[8 * t + 4 + lc];
        }
    }

    cp16(ksB + (unsigned)(r0c * 144 + c0c * 2), kg + (size_t)r0c * DK_ + c0c);
    cp16(ksB + (unsigned)(r1c * 144 + c1c * 2), kg + (size_t)r1c * DK_ + c1c);
    cp16(vsB + (unsigned)(r0c * 144 + c0c * 2), vg + (size_t)r0c * DK_ + c0c);
    cp16(vsB + (unsigned)(r1c * 144 + c1c * 2), vg + (size_t)r1c * DK_ + c1c);
    cp_commit();

    float o[8][4];
    float m[2], l[2];
    m[0] = -1e30f; m[1] = -1e30f; l[0] = 0.f; l[1] = 0.f;
    #pragma unroll
    for (int ni = 0; ni < 8; ni++)
        #pragma unroll
        for (int q = 0; q < 4; q++) o[ni][q] = 0.f;

    for (int kb = 0; kb < S_ / 64; kb++) {
        int buf = kb & 1;
        if (kb + 1 < S_ / 64) {
            int nb = buf ^ 1;
            size_t k0n = (size_t)(kb + 1) * 64;
            cp16(ksB + (unsigned)((nb * 64 + r0c) * 144 + c0c * 2), kg + (k0n + r0c) * DK_ + c0c);
            cp16(ksB + (unsigned)((nb * 64 + r1c) * 144 + c1c * 2), kg + (k0n + r1c) * DK_ + c1c);
            cp16(vsB + (unsigned)((nb * 64 + r0c) * 144 + c0c * 2), vg + (k0n + r0c) * DK_ + c0c);
            cp16(vsB + (unsigned)((nb * 64 + r1c) * 144 + c1c * 2), vg + (k0n + r1c) * DK_ + c1c);
            cp_commit();
            cp_wait<1>();
        } else {
            cp_wait<0>();
        }
        __syncthreads();

        unsigned kbase = ksB + (unsigned)(buf * 64) * 144;
        unsigned vbase = vsB + (unsigned)(buf * 64) * 144;

        float s[8][4];
        #pragma unroll
        for (int ni = 0; ni < 8; ni++)
            #pragma unroll
            for (int q = 0; q < 4; q++) s[ni][q] = 0.f;

        #pragma unroll
        for (int t = 0; t < 4; t++) {
            #pragma unroll
            for (int np = 0; np < 4; np++) {
                unsigned bf[4];
                ldsm4(bf, kbase + (unsigned)((np * 16 + rowK) * 144 + t * 32 + colK));
                mma16(s[2 * np],     qf[t], &bf[0]);
                mma16(s[2 * np + 1], qf[t], &bf[2]);
            }
        }

        #pragma unroll
        for (int hh = 0; hh < 2; hh++) {
            int grow = q0 + rb + hh * 8 + lr;
            uint2 w = *(const uint2*)(mw + ((size_t)b * S_ + grow) * (S_ / 32) + kb * 2);
            float rmax = -1e30f;
            #pragma unroll
            for (int ni = 0; ni < 8; ni++) {
                int col = ni * 8 + 2 * lc;
                unsigned ws = (col < 32) ? w.x : w.y;
                int bit = col & 31;
                float* sp = &s[ni][hh * 2];
                if (!((ws >> bit) & 1u))       sp[0] = -1e9f;
                if (!((ws >> (bit + 1)) & 1u)) sp[1] = -1e9f;
                rmax = fmaxf(rmax, fmaxf(sp[0], sp[1]));
            }
            rmax = fmaxf(rmax, __shfl_xor_sync(0xffffffffu, rmax, 1));
            rmax = fmaxf(rmax, __shfl_xor_sync(0xffffffffu, rmax, 2));
            float mn = fmaxf(m[hh], rmax);
            float corr = __expf(m[hh] - mn);
            m[hh] = mn;
            float rs = 0.f;
            #pragma unroll
            for (int ni = 0; ni < 8; ni++) {
                float* sp = &s[ni][hh * 2];
                float p0 = __expf(sp[0] - mn);
                float p1 = __expf(sp[1] - mn);
                rs += p0 + p1;
                sp[0] = p0; sp[1] = p1;
                o[ni][hh * 2]     *= corr;
                o[ni][hh * 2 + 1] *= corr;
            }
            rs += __shfl_xor_sync(0xffffffffu, rs, 1);
            rs += __shfl_xor_sync(0xffffffffu, rs, 2);
            l[hh] = l[hh] * corr + rs;
        }

        #pragma unroll
        for (int t = 0; t < 4; t++) {
            unsigned a[4];
            a[0] = f2h2(s[2 * t][0],     s[2 * t][1]);
            a[1] = f2h2(s[2 * t][2],     s[2 * t][3]);
            a[2] = f2h2(s[2 * t + 1][0], s[2 * t + 1][1]);
            a[3] = f2h2(s[2 * t + 1][2], s[2 * t + 1][3]);
            #pragma unroll
            for (int np = 0; np < 4; np++) {
                unsigned bf[4];
                ldsm4t(bf, vbase + (unsigned)((t * 16 + rowV) * 144 + np * 32 + colV));
                mma16(o[2 * np],     a, &bf[0]);
                mma16(o[2 * np + 1], a, &bf[2]);
            }
        }
        __syncthreads();
    }

    #pragma unroll
    for (int hh = 0; hh < 2; hh++) {
        float inv = 1.0f / l[hh];
        int grow = q0 + rb + hh * 8 + lr;
        #pragma unroll
        for (int ni = 0; ni < 8; ni++) {
            int col = ni * 8 + 2 * lc;
            *(unsigned*)(out + ((size_t)(b * S_ + grow)) * D_ + h * DK_ + col) =
                f2h2(o[ni][hh * 2] * inv, o[ni][hh * 2 + 1] * inv);
        }
    }
}

// --------------------------------- host ---------------------------------------------
extern "C" void kernel_launch(void* const* d_in, const int* in_sizes, int n_in,
                              void* d_out, int out_size) {
    const float* query = (const float*)d_in[0];
    const float* key   = (const float*)d_in[1];
    const float* value = (const float*)d_in[2];
    const int*   mask  = (const int*)d_in[3];
    const float* lAq   = (const float*)d_in[4];
    const float* lBq   = (const float*)d_in[5];
    const float* lAv   = (const float*)d_in[6];
    const float* lBv   = (const float*)d_in[7];
    const float* Wq    = (const float*)d_in[8];
    const float* bq    = (const float*)d_in[9];
    const float* Wk    = (const float*)d_in[10];
    const float* bk    = (const float*)d_in[11];
    const float* Wv    = (const float*)d_in[12];
    const float* bv    = (const float*)d_in[13];
    const float* Wm    = (const float*)d_in[14];
    const float* bm    = (const float*)d_in[15];

    void *pAq, *pAv, *pQadjh, *pVadjh, *pkeyh, *pWh, *pqh, *pkh, *pvh, *paoh, *pmw;
    cudaGetSymbolAddress(&pAq,    g_Aq);
    cudaGetSymbolAddress(&pAv,    g_Av);
    cudaGetSymbolAddress(&pQadjh, g_Qadjh);
    cudaGetSymbolAddress(&pVadjh, g_Vadjh);
    cudaGetSymbolAddress(&pkeyh,  g_keyh);
    cudaGetSymbolAddress(&pWh,    g_Wh);
    cudaGetSymbolAddress(&pqh,    g_qh);
    cudaGetSymbolAddress(&pkh,    g_kh);
    cudaGetSymbolAddress(&pvh,    g_vh);
    cudaGetSymbolAddress(&paoh,   g_aoh);
    cudaGetSymbolAddress(&pmw,    g_mw);

    const __half* Whv = (const __half*)pWh;
    const __half* Whk = Whv + WSZ;
    const __half* Whq = Whv + 2 * WSZ;
    const __half* Whm = Whv + 3 * WSZ;

    // mask pack (independent)
    mask_pack_kernel<<<(B_ * S_ * (S_ / 32)) / 256, 256>>>(mask, (unsigned*)pmw);

    // LoRA down (q and v fused)
    lora_down_kernel<<<dim3(N_ / 8, 2), 256>>>(query, value, lAq, lAv,
                                               (float*)pAq, (float*)pAv);

    // LoRA up (q,v) + key cvt + W cvt, one launch
    lora_up_kernel<<<dim3(N_ * D_ / 4 / 256, 4), 256>>>(
        query, value, key, Wv, Wk, Wq, Wm,
        (const float*)pAq, (const float*)pAv, lBq, lBv,
        (__half*)pQadjh, (__half*)pVadjh, (__half*)pkeyh, (__half*)pWh);

    // Fused projections (reference's stream swap preserved)
    cudaFuncSetAttribute(gemm3_kernel, cudaFuncAttributeMaxDynamicSharedMemorySize, GEMM_SMEM);
    cudaFuncSetAttribute(gemm1_kernel, cudaFuncAttributeMaxDynamicSharedMemorySize, GEMM_SMEM);
    Gemm3Args ga;
    ga.A[0] = (const __half*)pQadjh; ga.W[0] = Whv; ga.bias[0] = bv; ga.C[0] = (__half*)pvh; ga.scale[0] = 1.0f;
    ga.A[1] = (const __half*)pkeyh;  ga.W[1] = Whk; ga.bias[1] = bk; ga.C[1] = (__half*)pkh; ga.scale[1] = 1.0f;
    ga.A[2] = (const __half*)pVadjh; ga.W[2] = Whq; ga.bias[2] = bq; ga.C[2] = (__half*)pqh; ga.scale[2] = 0.125f;
    gemm3_kernel<<<dim3(N_ / 128, D_ / 256, 3), 256, GEMM_SMEM>>>(ga);

    // Flash attention -> fp16 ao (R12 config: 8 warps, strip 16)
    cudaFuncSetAttribute(attn_h_kernel, cudaFuncAttributeMaxDynamicSharedMemorySize, ATTN_SMEM);
    attn_h_kernel<<<dim3(S_ / 128, H_, B_), 256, ATTN_SMEM>>>((const unsigned*)pmw, (__half*)paoh);

    // Final: out = ao @ Wm^T + bm (fp32 out)
    gemm1_kernel<<<dim3(N_ / 128, D_ / 256), 256, GEMM_SMEM>>>((const __half*)paoh, Whm, bm, (float*)d_out);
}

// round 15
// speedup vs baseline: 1.0106x; 1.0024x over previous
#include <cuda_runtime.h>
#include <cuda_fp16.h>
#include <cstdint>

#define B_ 2
#define S_ 2048
#define D_ 768
#define H_ 12
#define DK_ 64
#define R_ 8
#define N_ 4096   // B_*S_
#define WSZ (D_ * D_)
#define LOG2E 1.4426950408889634f

// ---------------- scratch (static device globals; no allocation) ----------------
__device__ __align__(256) __half g_Qadjh[(size_t)N_ * D_];
__device__ __align__(256) __half g_Vadjh[(size_t)N_ * D_];
__device__ __align__(256) __half g_keyh[(size_t)N_ * D_];
__device__ __align__(256) __half g_Wh[(size_t)4 * WSZ];   // [Wv, Wk, Wq, Wm] fp16
__device__ __align__(256) __half g_qh[(size_t)N_ * D_];   // [B,H,S,DK], pre-scaled 0.125*log2e
__device__ __align__(256) __half g_kh[(size_t)N_ * D_];
__device__ __align__(256) __half g_vh[(size_t)N_ * D_];
__device__ __align__(256) __half g_aoh[(size_t)N_ * D_];  // [B,S,D] fp16
__device__ unsigned g_mw[B_ * S_ * (S_ / 32)];

// ---------------- helpers ----------------------------------------------------------
__device__ __forceinline__ unsigned f2h2(float a, float b) {   // lo=a, hi=b
    unsigned r;
    asm("cvt.rn.f16x2.f32 %0, %1, %2;" : "=r"(r) : "f"(b), "f"(a));
    return r;
}
__device__ __forceinline__ uint2 cvt4h(float4 v) {
    return make_uint2(f2h2(v.x, v.y), f2h2(v.z, v.w));
}
__device__ __forceinline__ float ex2(float x) {
    float r;
    asm("ex2.approx.f32 %0, %1;" : "=f"(r) : "f"(x));
    return r;
}
__device__ __forceinline__ void mma16(float* c, const unsigned* a, const unsigned* b) {
    asm volatile(
        "mma.sync.aligned.m16n8k16.row.col.f32.f16.f16.f32 "
        "{%0,%1,%2,%3}, {%4,%5,%6,%7}, {%8,%9}, {%0,%1,%2,%3};"
        : "+f"(c[0]), "+f"(c[1]), "+f"(c[2]), "+f"(c[3])
        : "r"(a[0]), "r"(a[1]), "r"(a[2]), "r"(a[3]), "r"(b[0]), "r"(b[1]));
}
__device__ __forceinline__ void ldsm4(unsigned* r, unsigned addr) {
    asm volatile("ldmatrix.sync.aligned.m8n8.x4.shared.b16 {%0,%1,%2,%3}, [%4];"
                 : "=r"(r[0]), "=r"(r[1]), "=r"(r[2]), "=r"(r[3]) : "r"(addr));
}
__device__ __forceinline__ void ldsm4t(unsigned* r, unsigned addr) {
    asm volatile("ldmatrix.sync.aligned.m8n8.x4.trans.shared.b16 {%0,%1,%2,%3}, [%4];"
                 : "=r"(r[0]), "=r"(r[1]), "=r"(r[2]), "=r"(r[3]) : "r"(addr));
}
__device__ __forceinline__ void cp16(unsigned dst, const void* src) {
    asm volatile("cp.async.cg.shared.global [%0], [%1], 16;" :: "r"(dst), "l"(src));
}
__device__ __forceinline__ void cp_commit() { asm volatile("cp.async.commit_group;"); }
template <int NN>
__device__ __forceinline__ void cp_wait() {
    asm volatile("cp.async.wait_group %0;" :: "n"(NN));
}

// ---- K0: fused lora down+up: out = fp16(x + (x@A)@Bm), per-stream via blockIdx.y --
// 128 threads = 4 warps; 16 rows per block; A transposed + Bm staged in smem.
#define LORA_SMEM (2 * 8 * 768 * 4)
__global__ void __launch_bounds__(128)
lora_fused_kernel(const float* __restrict__ xq, const float* __restrict__ xv,
                  const float* __restrict__ Aq, const float* __restrict__ Av,
                  const float* __restrict__ Bq, const float* __restrict__ Bv,
                  __half* __restrict__ oq, __half* __restrict__ ov) {
    extern __shared__ float lsm[];
    float* sAT = lsm;            // [8][768]  A^T
    float* sB  = lsm + 8 * 768;  // [8][768]  Bm
    const float* x  = blockIdx.y ? xv : xq;
    const float* A  = blockIdx.y ? Av : Aq;
    const float* Bm = blockIdx.y ? Bv : Bq;
    __half* out     = blockIdx.y ? ov : oq;
    int tid = threadIdx.x, warp = tid >> 5, lane = tid & 31;

    for (int i = tid; i < 1536; i += 128) {   // A: 768x8 -> transposed
        int k = i >> 1, rh = (i & 1) * 4;
        float4 v = *(const float4*)(A + k * 8 + rh);
        sAT[(rh + 0) * 768 + k] = v.x;
        sAT[(rh + 1) * 768 + k] = v.y;
        sAT[(rh + 2) * 768 + k] = v.z;
        sAT[(rh + 3) * 768 + k] = v.w;
    }
    for (int i = tid; i < 1536; i += 128)     // Bm: 8x768 as-is
        *(float4*)&sB[i * 4] = *(const float4*)(Bm + i * 4);
    __syncthreads();

    int row0 = blockIdx.x * 16 + warp * 4;
    for (int rr = 0; rr < 4; rr++) {
        int row = row0 + rr;
        const float* xr = x + (size_t)row * 768;
        float xv_[6][4];
        #pragma unroll
        for (int p = 0; p < 6; p++)
            *(float4*)xv_[p] = *(const float4*)(xr + p * 128 + lane * 4);

        float acc[8];
        #pragma unroll
        for (int r = 0; r < 8; r++) acc[r] = 0.f;
        #pragma unroll
        for (int p = 0; p < 6; p++) {
            int k = p * 128 + lane * 4;
            #pragma unroll
            for (int r = 0; r < 8; r++) {
                float4 av = *(const float4*)&sAT[r * 768 + k];
                acc[r] += xv_[p][0] * av.x + xv_[p][1] * av.y
                        + xv_[p][2] * av.z + xv_[p][3] * av.w;
            }
        }
        #pragma unroll
        for (int r = 0; r < 8; r++) {
            #pragma unroll
            for (int off = 16; off > 0; off >>= 1)
                acc[r] += __shfl_xor_sync(0xffffffffu, acc[r], off);
        }
        #pragma unroll
        for (int p = 0; p < 6; p++) {
            int c = p * 128 + lane * 4;
            float4 s4 = *(float4*)xv_[p];
            #pragma unroll
            for (int r = 0; r < 8; r++) {
                float4 bv = *(const float4*)&sB[r * 768 + c];
                s4.x += acc[r] * bv.x; s4.y += acc[r] * bv.y;
                s4.z += acc[r] * bv.z; s4.w += acc[r] * bv.w;
            }
            *(uint2*)(out + (size_t)row * 768 + c) = cvt4h(s4);
        }
    }
}

// ---- K1: fp32->fp16 convert for key (y=0) and the 4 W matrices (y=1) --------------
__global__ void cvt_kernel(const float* __restrict__ key,
                           const float* __restrict__ Wv_, const float* __restrict__ Wk_,
                           const float* __restrict__ Wq_, const float* __restrict__ Wm_,
                           __half* __restrict__ okey, __half* __restrict__ oW) {
    int i4 = blockIdx.x * blockDim.x + threadIdx.x;
    if (blockIdx.y == 0) {
        size_t off = (size_t)i4 * 4;
        *(uint2*)(okey + off) = cvt4h(*(const float4*)(key + off));
    } else {
        if (i4 >= 4 * WSZ / 4) return;
        int which = i4 / (WSZ / 4);
        size_t off = (size_t)(i4 - which * (WSZ / 4)) * 4;
        const float* src = which == 0 ? Wv_ : which == 1 ? Wk_ : which == 2 ? Wq_ : Wm_;
        *(uint2*)(oW + (size_t)which * WSZ + off) = cvt4h(*(const float4*)(src + off));
    }
}

// -------- K1b: pack mask ints into bits ---------------------------------------------
__global__ void mask_pack_kernel(const int* __restrict__ mask,
                                 unsigned* __restrict__ mw) {
    int w = blockIdx.x * blockDim.x + threadIdx.x;
    const int4* mp = (const int4*)(mask + (size_t)w * 32);
    unsigned bits = 0;
    #pragma unroll
    for (int j = 0; j < 8; j++) {
        int4 v = mp[j];
        bits |= (v.x != 0 ? 1u : 0u) << (j * 4 + 0);
        bits |= (v.y != 0 ? 1u : 0u) << (j * 4 + 1);
        bits |= (v.z != 0 ? 1u : 0u) << (j * 4 + 2);
        bits |= (v.w != 0 ? 1u : 0u) << (j * 4 + 3);
    }
    mw[w] = bits;
}

// ---- GEMM body: all-fp16, BM=128, BN=256, BK=32; 8 warps 2m x 4n (R14) -----------
#define GSTW 20
#define GEMM_SMEM ((2 * 128 + 2 * 256) * GSTW * 4)
__device__ __forceinline__ void gemm_body(
    const __half* __restrict__ A, const __half* __restrict__ W,
    const float* __restrict__ bias, void* __restrict__ Cv,
    float scale, int headPermute, int bx, int by,
    unsigned* As, unsigned* Bs) {

    int tid = threadIdx.x;
    int warp = tid >> 5, lane = tid & 31;
    int wm = warp & 1, wn = warp >> 1;
    int lr = lane >> 2, lc = lane & 3;
    int i0 = bx * 128, n0 = by * 256;

    int mIdx = lane >> 3, l7 = lane & 7;
    int rowA = ((mIdx & 1) << 3) + l7, colA = (mIdx >> 1) << 4;
    int rowB = ((mIdx >> 1) << 3) + l7, colB = (mIdx & 1) << 4;
    unsigned asB = (unsigned)__cvta_generic_to_shared(As);
    unsigned bsB = (unsigned)__cvta_generic_to_shared(Bs);

    int arow = tid >> 1, aseg = (tid & 1) << 4;
    const __half* Ap = A + (size_t)(i0 + arow) * D_ + aseg;
    int akw = aseg >> 1;
    const __half* Wp = W + (size_t)(n0 + tid) * D_;

    float c[4][8][4];
    #pragma unroll
    for (int mi = 0; mi < 4; mi++)
        #pragma unroll
        for (int nj = 0; nj < 8; nj++)
            #pragma unroll
            for (int q = 0; q < 4; q++) c[mi][nj][q] = 0.f;

    uint4 rah[2], rbh[4];
    rah[0] = *(const uint4*)Ap;        rah[1] = *(const uint4*)(Ap + 8);
    #pragma unroll
    for (int p = 0; p < 4; p++) rbh[p] = *(const uint4*)(Wp + 8 * p);
    *(uint4*)&As[arow * GSTW + akw] = rah[0];
    *(uint4*)&As[arow * GSTW + akw + 4] = rah[1];
    #pragma unroll
    for (int p = 0; p < 4; p++) *(uint4*)&Bs[tid * GSTW + 4 * p] = rbh[p];
    __syncthreads();

    for (int it = 0; it < 24; it++) {
        int buf = it & 1;
        if (it < 23) {
            int k0 = (it + 1) * 32;
            rah[0] = *(const uint4*)(Ap + k0);  rah[1] = *(const uint4*)(Ap + k0 + 8);
            #pragma unroll
            for (int p = 0; p < 4; p++) rbh[p] = *(const uint4*)(Wp + k0 + 8 * p);
        }

        #pragma unroll
        for (int t = 0; t < 2; t++) {
            unsigned af[4][4], bb[4][4];
            #pragma unroll
            for (int mi = 0; mi < 4; mi++)
                ldsm4(af[mi], asB + (unsigned)((buf * 128 + wm * 64 + mi * 16 + rowA) * 80 + t * 32 + colA));
            #pragma unroll
            for (int np = 0; np < 4; np++)
                ldsm4(bb[np], bsB + (unsigned)((buf * 256 + wn * 64 + np * 16 + rowB) * 80 + t * 32 + colB));
            #pragma unroll
            for (int mi = 0; mi < 4; mi++)
                #pragma unroll
                for (int np = 0; np < 4; np++) {
                    mma16(c[mi][2 * np],     af[mi], &bb[np][0]);
                    mma16(c[mi][2 * np + 1], af[mi], &bb[np][2]);
                }
        }

        if (it < 23) {
            int nb = buf ^ 1;
            *(uint4*)&As[(nb * 128 + arow) * GSTW + akw] = rah[0];
            *(uint4*)&As[(nb * 128 + arow) * GSTW + akw + 4] = rah[1];
            #pragma unroll
            for (int p = 0; p < 4; p++)
                *(uint4*)&Bs[(nb * 256 + tid) * GSTW + 4 * p] = rbh[p];
        }
        __syncthreads();
    }

    #pragma unroll
    for (int mi = 0; mi < 4; mi++) {
        #pragma unroll
        for (int nj = 0; nj < 8; nj++) {
            int i = i0 + wm * 64 + mi * 16 + lr;
            int j = n0 + wn * 64 + nj * 8 + 2 * lc;
            float b0 = bias[j], b1 = bias[j + 1];
            float v00 = scale * (c[mi][nj][0] + b0), v01 = scale * (c[mi][nj][1] + b1);
            float v10 = scale * (c[mi][nj][2] + b0), v11 = scale * (c[mi][nj][3] + b1);
            if (headPermute) {
                __half* Ch = (__half*)Cv;
                int bb2 = i >> 11, s = i & 2047;
                int hh = j >> 6, dk = j & 63;
                *(unsigned*)(Ch + (((size_t)(bb2 * H_ + hh)) * S_ + s) * DK_ + dk) = f2h2(v00, v01);
                *(unsigned*)(Ch + (((size_t)(bb2 * H_ + hh)) * S_ + (s + 8)) * DK_ + dk) = f2h2(v10, v11);
            } else {
                float* Cf = (float*)Cv;
                *(float2*)(Cf + (size_t)i * D_ + j) = make_float2(v00, v01);
                *(float2*)(Cf + (size_t)(i + 8) * D_ + j) = make_float2(v10, v11);
            }
        }
    }
}

struct Gemm3Args {
    const __half* A[3];
    const __half* W[3];
    const float*  bias[3];
    __half*       C[3];
    float         scale[3];
};
__global__ void __launch_bounds__(256, 1)
gemm3_kernel(Gemm3Args args) {
    extern __shared__ unsigned gsm[];
    unsigned* As = gsm;
    unsigned* Bs = gsm + 2 * 128 * GSTW;
    int z = blockIdx.z;
    gemm_body(args.A[z], args.W[z], args.bias[z], args.C[z], args.scale[z], 1,
              blockIdx.x, blockIdx.y, As, Bs);
}

__global__ void __launch_bounds__(256, 1)
gemm1_kernel(const __half* __restrict__ A, const __half* __restrict__ W,
             const float* __restrict__ bias, float* __restrict__ C) {
    extern __shared__ unsigned gsm[];
    unsigned* As = gsm;
    unsigned* Bs = gsm + 2 * 128 * GSTW;
    gemm_body(A, W, bias, C, 1.0f, 0, blockIdx.x, blockIdx.y, As, Bs);
}

// ---------------- K3: flash attention — 8 warps, strip 16, exp2 softmax ------------
#define ASTW 36
#define ATTN_SMEM (4 * 64 * ASTW * 4)
__global__ void __launch_bounds__(256, 2)
attn_h_kernel(const unsigned* __restrict__ mw, __half* __restrict__ out) {
    extern __shared__ unsigned sm[];
    unsigned* Ks = sm;
    unsigned* Vs = sm + 2 * 64 * ASTW;

    int tid = threadIdx.x, warp = tid >> 5, lane = tid & 31;
    int lr = lane >> 2, lc = lane & 3;
    int rb = warp * 16;
    int qb = blockIdx.x, h = blockIdx.y, b = blockIdx.z;
    int q0 = qb * 128, bh = b * H_ + h;

    const __half* qg = g_qh + ((size_t)bh * S_ + q0) * DK_;
    const __half* kg = g_kh + (size_t)bh * S_ * DK_;
    const __half* vg = g_vh + (size_t)bh * S_ * DK_;

    int mIdx = lane >> 3, l7 = lane & 7;
    int rowK = ((mIdx >> 1) << 3) + l7, colK = (mIdx & 1) << 4;
    int rowV = ((mIdx & 1) << 3) + l7, colV = (mIdx >> 1) << 4;
    unsigned ksB = (unsigned)__cvta_generic_to_shared(Ks);
    unsigned vsB = (unsigned)__cvta_generic_to_shared(Vs);

    int r0c = tid >> 3, c0c = (tid & 7) << 3;
    int r1c = (tid + 256) >> 3, c1c = c0c;

    unsigned qf[4][4];
    {
        const unsigned* u0 = (const unsigned*)(qg + (size_t)(rb + lr) * DK_);
        const unsigned* u1 = (const unsigned*)(qg + (size_t)(rb + lr + 8) * DK_);
        #pragma unroll
        for (int t = 0; t < 4; t++) {
            qf[t][0] = u0[8 * t + lc];
            qf[t][1] = u1[8 * t + lc];
            qf[t][2] = u0[8 * t + 4 + lc];
            qf[t][3] = u1[8 * t + 4 + lc];
        }
    }

    cp16(ksB + (unsigned)(r0c * 144 + c0c * 2), kg + (size_t)r0c * DK_ + c0c);
    cp16(ksB + (unsigned)(r1c * 144 + c1c * 2), kg + (size_t)r1c * DK_ + c1c);
    cp16(vsB + (unsigned)(r0c * 144 + c0c * 2), vg + (size_t)r0c * DK_ + c0c);
    cp16(vsB + (unsigned)(r1c * 144 + c1c * 2), vg + (size_t)r1c * DK_ + c1c);
    cp_commit();

    float o[8][4];
    float m[2], l[2];
    m[0] = -1e30f; m[1] = -1e30f; l[0] = 0.f; l[1] = 0.f;
    #pragma unroll
    for (int ni = 0; ni < 8; ni++)
        #pragma unroll
        for (int q = 0; q < 4; q++) o[ni][q] = 0.f;

    for (int kb = 0; kb < S_ / 64; kb++) {
        int buf = kb & 1;
        if (kb + 1 < S_ / 64) {
            int nb = buf ^ 1;
            size_t k0n = (size_t)(kb + 1) * 64;
            cp16(ksB + (unsigned)((nb * 64 + r0c) * 144 + c0c * 2), kg + (k0n + r0c) * DK_ + c0c);
            cp16(ksB + (unsigned)((nb * 64 + r1c) * 144 + c1c * 2), kg + (k0n + r1c) * DK_ + c1c);
            cp16(vsB + (unsigned)((nb * 64 + r0c) * 144 + c0c * 2), vg + (k0n + r0c) * DK_ + c0c);
            cp16(vsB + (unsigned)((nb * 64 + r1c) * 144 + c1c * 2), vg + (k0n + r1c) * DK_ + c1c);
            cp_commit();
            cp_wait<1>();
        } else {
            cp_wait<0>();
        }
        __syncthreads();

        unsigned kbase = ksB + (unsigned)(buf * 64) * 144;
        unsigned vbase = vsB + (unsigned)(buf * 64) * 144;

        float s[8][4];
        #pragma unroll
        for (int ni = 0; ni < 8; ni++)
            #pragma unroll
            for (int q = 0; q < 4; q++) s[ni][q] = 0.f;

        #pragma unroll
        for (int t = 0; t < 4; t++) {
            #pragma unroll
            for (int np = 0; np < 4; np++) {
                unsigned bf[4];
                ldsm4(bf, kbase + (unsigned)((np * 16 + rowK) * 144 + t * 32 + colK));
                mma16(s[2 * np],     qf[t], &bf[0]);
                mma16(s[2 * np + 1], qf[t], &bf[2]);
            }
        }

        #pragma unroll
        for (int hh = 0; hh < 2; hh++) {
            int grow = q0 + rb + hh * 8 + lr;
            uint2 w = *(const uint2*)(mw + ((size_t)b * S_ + grow) * (S_ / 32) + kb * 2);
            float rmax = -1e30f;
            #pragma unroll
            for (int ni = 0; ni < 8; ni++) {
                int col = ni * 8 + 2 * lc;
                unsigned ws = (col < 32) ? w.x : w.y;
                int bit = col & 31;
                float* sp = &s[ni][hh * 2];
                if (!((ws >> bit) & 1u))       sp[0] = -1e9f;
                if (!((ws >> (bit + 1)) & 1u)) sp[1] = -1e9f;
                rmax = fmaxf(rmax, fmaxf(sp[0], sp[1]));
            }
            rmax = fmaxf(rmax, __shfl_xor_sync(0xffffffffu, rmax, 1));
            rmax = fmaxf(rmax, __shfl_xor_sync(0xffffffffu, rmax, 2));
            float mn = fmaxf(m[hh], rmax);
            float corr = ex2(m[hh] - mn);
            m[hh] = mn;
            float rs = 0.f;
            #pragma unroll
            for (int ni = 0; ni < 8; ni++) {
                float* sp = &s[ni][hh * 2];
                float p0 = ex2(sp[0] - mn);
                float p1 = ex2(sp[1] - mn);
                rs += p0 + p1;
                sp[0] = p0; sp[1] = p1;
                o[ni][hh * 2]     *= corr;
                o[ni][hh * 2 + 1] *= corr;
            }
            rs += __shfl_xor_sync(0xffffffffu, rs, 1);
            rs += __shfl_xor_sync(0xffffffffu, rs, 2);
            l[hh] = l[hh] * corr + rs;
        }

        #pragma unroll
        for (int t = 0; t < 4; t++) {
            unsigned a[4];
            a[0] = f2h2(s[2 * t][0],     s[2 * t][1]);
            a[1] = f2h2(s[2 * t][2],     s[2 * t][3]);
            a[2] = f2h2(s[2 * t + 1][0], s[2 * t + 1][1]);
            a[3] = f2h2(s[2 * t + 1][2], s[2 * t + 1][3]);
            #pragma unroll
            for (int np = 0; np < 4; np++) {
                unsigned bf[4];
                ldsm4t(bf, vbase + (unsigned)((t * 16 + rowV) * 144 + np * 32 + colV));
                mma16(o[2 * np],     a, &bf[0]);
                mma16(o[2 * np + 1], a, &bf[2]);
            }
        }
        __syncthreads();
    }

    #pragma unroll
    for (int hh = 0; hh < 2; hh++) {
        float inv = 1.0f / l[hh];
        int grow = q0 + rb + hh * 8 + lr;
        #pragma unroll
        for (int ni = 0; ni < 8; ni++) {
            int col = ni * 8 + 2 * lc;
            *(unsigned*)(out + ((size_t)(b * S_ + grow)) * D_ + h * DK_ + col) =
                f2h2(o[ni][hh * 2] * inv, o[ni][hh * 2 + 1] * inv);
        }
    }
}

// --------------------------------- host ---------------------------------------------
extern "C" void kernel_launch(void* const* d_in, const int* in_sizes, int n_in,
                              void* d_out, int out_size) {
    const float* query = (const float*)d_in[0];
    const float* key   = (const float*)d_in[1];
    const float* value = (const float*)d_in[2];
    const int*   mask  = (const int*)d_in[3];
    const float* lAq   = (const float*)d_in[4];
    const float* lBq   = (const float*)d_in[5];
    const float* lAv   = (const float*)d_in[6];
    const float* lBv   = (const float*)d_in[7];
    const float* Wq    = (const float*)d_in[8];
    const float* bq    = (const float*)d_in[9];
    const float* Wk    = (const float*)d_in[10];
    const float* bk    = (const float*)d_in[11];
    const float* Wv    = (const float*)d_in[12];
    const float* bv    = (const float*)d_in[13];
    const float* Wm    = (const float*)d_in[14];
    const float* bm    = (const float*)d_in[15];

    void *pQadjh, *pVadjh, *pkeyh, *pWh, *pqh, *pkh, *pvh, *paoh, *pmw;
    cudaGetSymbolAddress(&pQadjh, g_Qadjh);
    cudaGetSymbolAddress(&pVadjh, g_Vadjh);
    cudaGetSymbolAddress(&pkeyh,  g_keyh);
    cudaGetSymbolAddress(&pWh,    g_Wh);
    cudaGetSymbolAddress(&pqh,    g_qh);
    cudaGetSymbolAddress(&pkh,    g_kh);
    cudaGetSymbolAddress(&pvh,    g_vh);
    cudaGetSymbolAddress(&paoh,   g_aoh);
    cudaGetSymbolAddress(&pmw,    g_mw);

    const __half* Whv = (const __half*)pWh;
    const __half* Whk = Whv + WSZ;
    const __half* Whq = Whv + 2 * WSZ;
    const __half* Whm = Whv + 3 * WSZ;

    // mask pack (independent)
    mask_pack_kernel<<<(B_ * S_ * (S_ / 32)) / 256, 256>>>(mask, (unsigned*)pmw);

    // key + W fp16 converts
    cvt_kernel<<<dim3(N_ * D_ / 4 / 256, 2), 256>>>(
        key, Wv, Wk, Wq, Wm, (__half*)pkeyh, (__half*)pWh);

    // fused LoRA down+up (q and v via gridDim.y)
    cudaFuncSetAttribute(lora_fused_kernel, cudaFuncAttributeMaxDynamicSharedMemorySize, LORA_SMEM);
    lora_fused_kernel<<<dim3(N_ / 16, 2), 128, LORA_SMEM>>>(
        query, value, lAq, lAv, lBq, lBv, (__half*)pQadjh, (__half*)pVadjh);

    // Fused projections (reference's stream swap preserved); q scaled by 0.125*log2e
    cudaFuncSetAttribute(gemm3_kernel, cudaFuncAttributeMaxDynamicSharedMemorySize, GEMM_SMEM);
    cudaFuncSetAttribute(gemm1_kernel, cudaFuncAttributeMaxDynamicSharedMemorySize, GEMM_SMEM);
    Gemm3Args ga;
    ga.A[0] = (const __half*)pQadjh; ga.W[0] = Whv; ga.bias[0] = bv; ga.C[0] = (__half*)pvh; ga.scale[0] = 1.0f;
    ga.A[1] = (const __half*)pkeyh;  ga.W[1] = Whk; ga.bias[1] = bk; ga.C[1] = (__half*)pkh; ga.scale[1] = 1.0f;
    ga.A[2] = (const __half*)pVadjh; ga.W[2] = Whq; ga.bias[2] = bq; ga.C[2] = (__half*)pqh; ga.scale[2] = 0.125f * LOG2E;
    gemm3_kernel<<<dim3(N_ / 128, D_ / 256, 3), 256, GEMM_SMEM>>>(ga);

    // Flash attention -> fp16 ao
    cudaFuncSetAttribute(attn_h_kernel, cudaFuncAttributeMaxDynamicSharedMemorySize, ATTN_SMEM);
    attn_h_kernel<<<dim3(S_ / 128, H_, B_), 256, ATTN_SMEM>>>((const unsigned*)pmw, (__half*)paoh);

    // Final: out = ao @ Wm^T + bm (fp32 out)
    gemm1_kernel<<<dim3(N_ / 128, D_ / 256), 256, GEMM_SMEM>>>((const __half*)paoh, Whm, bm, (float*)d_out);
}

// round 16
// speedup vs baseline: 1.0138x; 1.0032x over previous
#include <cuda_runtime.h>
#include <cuda_fp16.h>
#include <cstdint>

#define B_ 2
#define S_ 2048
#define D_ 768
#define H_ 12
#define DK_ 64
#define R_ 8
#define N_ 4096   // B_*S_
#define WSZ (D_ * D_)
#define LOG2E 1.4426950408889634f

// ---------------- scratch (static device globals; no allocation) ----------------
__device__ __align__(256) __half g_Qadjh[(size_t)N_ * D_];
__device__ __align__(256) __half g_Vadjh[(size_t)N_ * D_];
__device__ __align__(256) __half g_keyh[(size_t)N_ * D_];
__device__ __align__(256) __half g_Wh[(size_t)4 * WSZ];   // [Wv, Wk, Wq, Wm] fp16
__device__ __align__(256) __half g_qh[(size_t)N_ * D_];   // [B,H,S,DK], pre-scaled 0.125*log2e
__device__ __align__(256) __half g_kh[(size_t)N_ * D_];
__device__ __align__(256) __half g_vh[(size_t)N_ * D_];
__device__ __align__(256) __half g_aoh[(size_t)N_ * D_];  // [B,S,D] fp16
__device__ unsigned g_mw[B_ * S_ * (S_ / 32)];

// ---------------- helpers ----------------------------------------------------------
__device__ __forceinline__ unsigned f2h2(float a, float b) {   // lo=a, hi=b
    unsigned r;
    asm("cvt.rn.f16x2.f32 %0, %1, %2;" : "=r"(r) : "f"(b), "f"(a));
    return r;
}
__device__ __forceinline__ uint2 cvt4h(float4 v) {
    return make_uint2(f2h2(v.x, v.y), f2h2(v.z, v.w));
}
__device__ __forceinline__ float ex2(float x) {
    float r;
    asm("ex2.approx.f32 %0, %1;" : "=f"(r) : "f"(x));
    return r;
}
__device__ __forceinline__ void mma16(float* c, const unsigned* a, const unsigned* b) {
    asm volatile(
        "mma.sync.aligned.m16n8k16.row.col.f32.f16.f16.f32 "
        "{%0,%1,%2,%3}, {%4,%5,%6,%7}, {%8,%9}, {%0,%1,%2,%3};"
        : "+f"(c[0]), "+f"(c[1]), "+f"(c[2]), "+f"(c[3])
        : "r"(a[0]), "r"(a[1]), "r"(a[2]), "r"(a[3]), "r"(b[0]), "r"(b[1]));
}
__device__ __forceinline__ void ldsm4(unsigned* r, unsigned addr) {
    asm volatile("ldmatrix.sync.aligned.m8n8.x4.shared.b16 {%0,%1,%2,%3}, [%4];"
                 : "=r"(r[0]), "=r"(r[1]), "=r"(r[2]), "=r"(r[3]) : "r"(addr));
}
__device__ __forceinline__ void ldsm4t(unsigned* r, unsigned addr) {
    asm volatile("ldmatrix.sync.aligned.m8n8.x4.trans.shared.b16 {%0,%1,%2,%3}, [%4];"
                 : "=r"(r[0]), "=r"(r[1]), "=r"(r[2]), "=r"(r[3]) : "r"(addr));
}
__device__ __forceinline__ void cp16(unsigned dst, const void* src) {
    asm volatile("cp.async.cg.shared.global [%0], [%1], 16;" :: "r"(dst), "l"(src));
}
__device__ __forceinline__ void cp_commit() { asm volatile("cp.async.commit_group;"); }
template <int NN>
__device__ __forceinline__ void cp_wait() {
    asm volatile("cp.async.wait_group %0;" :: "n"(NN));
}

// ---- K0: fused lora down+up: out = fp16(x + (x@A)@Bm), per-stream via blockIdx.y --
#define LORA_SMEM (2 * 8 * 768 * 4)
__global__ void __launch_bounds__(128)
lora_fused_kernel(const float* __restrict__ xq, const float* __restrict__ xv,
                  const float* __restrict__ Aq, const float* __restrict__ Av,
                  const float* __restrict__ Bq, const float* __restrict__ Bv,
                  __half* __restrict__ oq, __half* __restrict__ ov) {
    extern __shared__ float lsm[];
    float* sAT = lsm;            // [8][768]  A^T
    float* sB  = lsm + 8 * 768;  // [8][768]  Bm
    const float* x  = blockIdx.y ? xv : xq;
    const float* A  = blockIdx.y ? Av : Aq;
    const float* Bm = blockIdx.y ? Bv : Bq;
    __half* out     = blockIdx.y ? ov : oq;
    int tid = threadIdx.x, warp = tid >> 5, lane = tid & 31;

    for (int i = tid; i < 1536; i += 128) {   // A: 768x8 -> transposed
        int k = i >> 1, rh = (i & 1) * 4;
        float4 v = *(const float4*)(A + k * 8 + rh);
        sAT[(rh + 0) * 768 + k] = v.x;
        sAT[(rh + 1) * 768 + k] = v.y;
        sAT[(rh + 2) * 768 + k] = v.z;
        sAT[(rh + 3) * 768 + k] = v.w;
    }
    for (int i = tid; i < 1536; i += 128)     // Bm: 8x768 as-is
        *(float4*)&sB[i * 4] = *(const float4*)(Bm + i * 4);
    __syncthreads();

    int row0 = blockIdx.x * 16 + warp * 4;
    for (int rr = 0; rr < 4; rr++) {
        int row = row0 + rr;
        const float* xr = x + (size_t)row * 768;
        float xv_[6][4];
        #pragma unroll
        for (int p = 0; p < 6; p++)
            *(float4*)xv_[p] = *(const float4*)(xr + p * 128 + lane * 4);

        float acc[8];
        #pragma unroll
        for (int r = 0; r < 8; r++) acc[r] = 0.f;
        #pragma unroll
        for (int p = 0; p < 6; p++) {
            int k = p * 128 + lane * 4;
            #pragma unroll
            for (int r = 0; r < 8; r++) {
                float4 av = *(const float4*)&sAT[r * 768 + k];
                acc[r] += xv_[p][0] * av.x + xv_[p][1] * av.y
                        + xv_[p][2] * av.z + xv_[p][3] * av.w;
            }
        }
        #pragma unroll
        for (int r = 0; r < 8; r++) {
            #pragma unroll
            for (int off = 16; off > 0; off >>= 1)
                acc[r] += __shfl_xor_sync(0xffffffffu, acc[r], off);
        }
        #pragma unroll
        for (int p = 0; p < 6; p++) {
            int c = p * 128 + lane * 4;
            float4 s4 = *(float4*)xv_[p];
            #pragma unroll
            for (int r = 0; r < 8; r++) {
                float4 bv = *(const float4*)&sB[r * 768 + c];
                s4.x += acc[r] * bv.x; s4.y += acc[r] * bv.y;
                s4.z += acc[r] * bv.z; s4.w += acc[r] * bv.w;
            }
            *(uint2*)(out + (size_t)row * 768 + c) = cvt4h(s4);
        }
    }
}

// ---- K1: fp32->fp16 convert for key (y=0) and the 4 W matrices (y=1) --------------
__global__ void cvt_kernel(const float* __restrict__ key,
                           const float* __restrict__ Wv_, const float* __restrict__ Wk_,
                           const float* __restrict__ Wq_, const float* __restrict__ Wm_,
                           __half* __restrict__ okey, __half* __restrict__ oW) {
    int i4 = blockIdx.x * blockDim.x + threadIdx.x;
    if (blockIdx.y == 0) {
        size_t off = (size_t)i4 * 4;
        *(uint2*)(okey + off) = cvt4h(*(const float4*)(key + off));
    } else {
        if (i4 >= 4 * WSZ / 4) return;
        int which = i4 / (WSZ / 4);
        size_t off = (size_t)(i4 - which * (WSZ / 4)) * 4;
        const float* src = which == 0 ? Wv_ : which == 1 ? Wk_ : which == 2 ? Wq_ : Wm_;
        *(uint2*)(oW + (size_t)which * WSZ + off) = cvt4h(*(const float4*)(src + off));
    }
}

// -------- K1b: pack mask ints into bits ---------------------------------------------
__global__ void mask_pack_kernel(const int* __restrict__ mask,
                                 unsigned* __restrict__ mw) {
    int w = blockIdx.x * blockDim.x + threadIdx.x;
    const int4* mp = (const int4*)(mask + (size_t)w * 32);
    unsigned bits = 0;
    #pragma unroll
    for (int j = 0; j < 8; j++) {
        int4 v = mp[j];
        bits |= (v.x != 0 ? 1u : 0u) << (j * 4 + 0);
        bits |= (v.y != 0 ? 1u : 0u) << (j * 4 + 1);
        bits |= (v.z != 0 ? 1u : 0u) << (j * 4 + 2);
        bits |= (v.w != 0 ? 1u : 0u) << (j * 4 + 3);
    }
    mw[w] = bits;
}

// ---- GEMM body: all-fp16, BM=128, BN=128, BK=32 (R12 shape, fp16 B) ---------------
// 8 warps as 2m x 4n; warp tile 64x32. Register-prefetch double buffer.
#define GSTW 20   // words per 32-half row; row stride 80B
__device__ __forceinline__ void gemm_body(
    const __half* __restrict__ A, const __half* __restrict__ W,
    const float* __restrict__ bias, void* __restrict__ Cv,
    float scale, int headPermute, int bx, int by,
    unsigned* As, unsigned* Bs) {

    int tid = threadIdx.x;
    int warp = tid >> 5, lane = tid & 31;
    int wm = warp & 1, wn = warp >> 1;
    int lr = lane >> 2, lc = lane & 3;
    int i0 = bx * 128, n0 = by * 128;

    int mIdx = lane >> 3, l7 = lane & 7;
    int rowA = ((mIdx & 1) << 3) + l7, colA = (mIdx >> 1) << 4;
    int rowB = ((mIdx >> 1) << 3) + l7, colB = (mIdx & 1) << 4;
    unsigned asB = (unsigned)__cvta_generic_to_shared(As);
    unsigned bsB = (unsigned)__cvta_generic_to_shared(Bs);

    int arow = tid >> 1, aseg = (tid & 1) << 4;
    const __half* Ap = A + (size_t)(i0 + arow) * D_ + aseg;
    const __half* Wp = W + (size_t)(n0 + arow) * D_ + aseg;
    int akw = aseg >> 1;

    float c[4][4][4];
    #pragma unroll
    for (int mi = 0; mi < 4; mi++)
        #pragma unroll
        for (int ni = 0; ni < 4; ni++)
            #pragma unroll
            for (int q = 0; q < 4; q++) c[mi][ni][q] = 0.f;

    uint4 rah[2], rbh[2];
    rah[0] = *(const uint4*)Ap;       rah[1] = *(const uint4*)(Ap + 8);
    rbh[0] = *(const uint4*)Wp;       rbh[1] = *(const uint4*)(Wp + 8);
    *(uint4*)&As[arow * GSTW + akw] = rah[0];
    *(uint4*)&As[arow * GSTW + akw + 4] = rah[1];
    *(uint4*)&Bs[arow * GSTW + akw] = rbh[0];
    *(uint4*)&Bs[arow * GSTW + akw + 4] = rbh[1];
    __syncthreads();

    for (int it = 0; it < 24; it++) {
        int buf = it & 1;
        if (it < 23) {
            int k0 = (it + 1) * 32;
            rah[0] = *(const uint4*)(Ap + k0);  rah[1] = *(const uint4*)(Ap + k0 + 8);
            rbh[0] = *(const uint4*)(Wp + k0);  rbh[1] = *(const uint4*)(Wp + k0 + 8);
        }

        #pragma unroll
        for (int t = 0; t < 2; t++) {
            unsigned af[4][4], bb[2][4];
            #pragma unroll
            for (int mi = 0; mi < 4; mi++)
                ldsm4(af[mi], asB + (unsigned)((buf * 128 + wm * 64 + mi * 16 + rowA) * 80 + t * 32 + colA));
            #pragma unroll
            for (int np = 0; np < 2; np++)
                ldsm4(bb[np], bsB + (unsigned)((buf * 128 + wn * 32 + np * 16 + rowB) * 80 + t * 32 + colB));
            #pragma unroll
            for (int mi = 0; mi < 4; mi++)
                #pragma unroll
                for (int np = 0; np < 2; np++) {
                    mma16(c[mi][2 * np],     af[mi], &bb[np][0]);
                    mma16(c[mi][2 * np + 1], af[mi], &bb[np][2]);
                }
        }

        if (it < 23) {
            int nb = buf ^ 1;
            *(uint4*)&As[(nb * 128 + arow) * GSTW + akw] = rah[0];
            *(uint4*)&As[(nb * 128 + arow) * GSTW + akw + 4] = rah[1];
            *(uint4*)&Bs[(nb * 128 + arow) * GSTW + akw] = rbh[0];
            *(uint4*)&Bs[(nb * 128 + arow) * GSTW + akw + 4] = rbh[1];
        }
        __syncthreads();
    }

    #pragma unroll
    for (int mi = 0; mi < 4; mi++) {
        #pragma unroll
        for (int ni = 0; ni < 4; ni++) {
            int i = i0 + wm * 64 + mi * 16 + lr;
            int j = n0 + wn * 32 + ni * 8 + 2 * lc;
            float b0 = bias[j], b1 = bias[j + 1];
            float v00 = scale * (c[mi][ni][0] + b0), v01 = scale * (c[mi][ni][1] + b1);
            float v10 = scale * (c[mi][ni][2] + b0), v11 = scale * (c[mi][ni][3] + b1);
            if (headPermute) {
                __half* Ch = (__half*)Cv;
                int bb2 = i >> 11, s = i & 2047;
                int hh = j >> 6, dk = j & 63;
                *(unsigned*)(Ch + (((size_t)(bb2 * H_ + hh)) * S_ + s) * DK_ + dk) = f2h2(v00, v01);
                *(unsigned*)(Ch + (((size_t)(bb2 * H_ + hh)) * S_ + (s + 8)) * DK_ + dk) = f2h2(v10, v11);
            } else {
                float* Cf = (float*)Cv;
                *(float2*)(Cf + (size_t)i * D_ + j) = make_float2(v00, v01);
                *(float2*)(Cf + (size_t)(i + 8) * D_ + j) = make_float2(v10, v11);
            }
        }
    }
}

struct Gemm3Args {
    const __half* A[3];
    const __half* W[3];
    const float*  bias[3];
    __half*       C[3];
    float         scale[3];
};
__global__ void __launch_bounds__(256, 2)
gemm3_kernel(Gemm3Args args) {
    __shared__ unsigned As[2 * 128 * GSTW];
    __shared__ unsigned Bs[2 * 128 * GSTW];
    int z = blockIdx.z;
    gemm_body(args.A[z], args.W[z], args.bias[z], args.C[z], args.scale[z], 1,
              blockIdx.x, blockIdx.y, As, Bs);
}

__global__ void __launch_bounds__(256, 2)
gemm1_kernel(const __half* __restrict__ A, const __half* __restrict__ W,
             const float* __restrict__ bias, float* __restrict__ C) {
    __shared__ unsigned As[2 * 128 * GSTW];
    __shared__ unsigned Bs[2 * 128 * GSTW];
    gemm_body(A, W, bias, C, 1.0f, 0, blockIdx.x, blockIdx.y, As, Bs);
}

// ---------------- K3: flash attention — 8 warps, strip 16, exp2 softmax ------------
#define ASTW 36
#define ATTN_SMEM (4 * 64 * ASTW * 4)
__global__ void __launch_bounds__(256, 2)
attn_h_kernel(const unsigned* __restrict__ mw, __half* __restrict__ out) {
    extern __shared__ unsigned sm[];
    unsigned* Ks = sm;
    unsigned* Vs = sm + 2 * 64 * ASTW;

    int tid = threadIdx.x, warp = tid >> 5, lane = tid & 31;
    int lr = lane >> 2, lc = lane & 3;
    int rb = warp * 16;
    int qb = blockIdx.x, h = blockIdx.y, b = blockIdx.z;
    int q0 = qb * 128, bh = b * H_ + h;

    const __half* qg = g_qh + ((size_t)bh * S_ + q0) * DK_;
    const __half* kg = g_kh + (size_t)bh * S_ * DK_;
    const __half* vg = g_vh + (size_t)bh * S_ * DK_;

    int mIdx = lane >> 3, l7 = lane & 7;
    int rowK = ((mIdx >> 1) << 3) + l7, colK = (mIdx & 1) << 4;
    int rowV = ((mIdx & 1) << 3) + l7, colV = (mIdx >> 1) << 4;
    unsigned ksB = (unsigned)__cvta_generic_to_shared(Ks);
    unsigned vsB = (unsigned)__cvta_generic_to_shared(Vs);

    int r0c = tid >> 3, c0c = (tid & 7) << 3;
    int r1c = (tid + 256) >> 3, c1c = c0c;

    unsigned qf[4][4];
    {
        const unsigned* u0 = (const unsigned*)(qg + (size_t)(rb + lr) * DK_);
        const unsigned* u1 = (const unsigned*)(qg + (size_t)(rb + lr + 8) * DK_);
        #pragma unroll
        for (int t = 0; t < 4; t++) {
            qf[t][0] = u0[8 * t + lc];
            qf[t][1] = u1[8 * t + lc];
            qf[t][2] = u0[8 * t + 4 + lc];
            qf[t][3] = u1[8 * t + 4 + lc];
        }
    }

    cp16(ksB + (unsigned)(r0c * 144 + c0c * 2), kg + (size_t)r0c * DK_ + c0c);
    cp16(ksB + (unsigned)(r1c * 144 + c1c * 2), kg + (size_t)r1c * DK_ + c1c);
    cp16(vsB + (unsigned)(r0c * 144 + c0c * 2), vg + (size_t)r0c * DK_ + c0c);
    cp16(vsB + (unsigned)(r1c * 144 + c1c * 2), vg + (size_t)r1c * DK_ + c1c);
    cp_commit();

    float o[8][4];
    float m[2], l[2];
    m[0] = -1e30f; m[1] = -1e30f; l[0] = 0.f; l[1] = 0.f;
    #pragma unroll
    for (int ni = 0; ni < 8; ni++)
        #pragma unroll
        for (int q = 0; q < 4; q++) o[ni][q] = 0.f;

    for (int kb = 0; kb < S_ / 64; kb++) {
        int buf = kb & 1;
        if (kb + 1 < S_ / 64) {
            int nb = buf ^ 1;
            size_t k0n = (size_t)(kb + 1) * 64;
            cp16(ksB + (unsigned)((nb * 64 + r0c) * 144 + c0c * 2), kg + (k0n + r0c) * DK_ + c0c);
            cp16(ksB + (unsigned)((nb * 64 + r1c) * 144 + c1c * 2), kg + (k0n + r1c) * DK_ + c1c);
            cp16(vsB + (unsigned)((nb * 64 + r0c) * 144 + c0c * 2), vg + (k0n + r0c) * DK_ + c0c);
            cp16(vsB + (unsigned)((nb * 64 + r1c) * 144 + c1c * 2), vg + (k0n + r1c) * DK_ + c1c);
            cp_commit();
            cp_wait<1>();
        } else {
            cp_wait<0>();
        }
        __syncthreads();

        unsigned kbase = ksB + (unsigned)(buf * 64) * 144;
        unsigned vbase = vsB + (unsigned)(buf * 64) * 144;

        float s[8][4];
        #pragma unroll
        for (int ni = 0; ni < 8; ni++)
            #pragma unroll
            for (int q = 0; q < 4; q++) s[ni][q] = 0.f;

        #pragma unroll
        for (int t = 0; t < 4; t++) {
            #pragma unroll
            for (int np = 0; np < 4; np++) {
                unsigned bf[4];
                ldsm4(bf, kbase + (unsigned)((np * 16 + rowK) * 144 + t * 32 + colK));
                mma16(s[2 * np],     qf[t], &bf[0]);
                mma16(s[2 * np + 1], qf[t], &bf[2]);
            }
        }

        #pragma unroll
        for (int hh = 0; hh < 2; hh++) {
            int grow = q0 + rb + hh * 8 + lr;
            uint2 w = *(const uint2*)(mw + ((size_t)b * S_ + grow) * (S_ / 32) + kb * 2);
            float rmax = -1e30f;
            #pragma unroll
            for (int ni = 0; ni < 8; ni++) {
                int col = ni * 8 + 2 * lc;
                unsigned ws = (col < 32) ? w.x : w.y;
                int bit = col & 31;
                float* sp = &s[ni][hh * 2];
                if (!((ws >> bit) & 1u))       sp[0] = -1e9f;
                if (!((ws >> (bit + 1)) & 1u)) sp[1] = -1e9f;
                rmax = fmaxf(rmax, fmaxf(sp[0], sp[1]));
            }
            rmax = fmaxf(rmax, __shfl_xor_sync(0xffffffffu, rmax, 1));
            rmax = fmaxf(rmax, __shfl_xor_sync(0xffffffffu, rmax, 2));
            float mn = fmaxf(m[hh], rmax);
            float corr = ex2(m[hh] - mn);
            m[hh] = mn;
            float rs = 0.f;
            #pragma unroll
            for (int ni = 0; ni < 8; ni++) {
                float* sp = &s[ni][hh * 2];
                float p0 = ex2(sp[0] - mn);
                float p1 = ex2(sp[1] - mn);
                rs += p0 + p1;
                sp[0] = p0; sp[1] = p1;
                o[ni][hh * 2]     *= corr;
                o[ni][hh * 2 + 1] *= corr;
            }
            rs += __shfl_xor_sync(0xffffffffu, rs, 1);
            rs += __shfl_xor_sync(0xffffffffu, rs, 2);
            l[hh] = l[hh] * corr + rs;
        }

        #pragma unroll
        for (int t = 0; t < 4; t++) {
            unsigned a[4];
            a[0] = f2h2(s[2 * t][0],     s[2 * t][1]);
            a[1] = f2h2(s[2 * t][2],     s[2 * t][3]);
            a[2] = f2h2(s[2 * t + 1][0], s[2 * t + 1][1]);
            a[3] = f2h2(s[2 * t + 1][2], s[2 * t + 1][3]);
            #pragma unroll
            for (int np = 0; np < 4; np++) {
                unsigned bf[4];
                ldsm4t(bf, vbase + (unsigned)((t * 16 + rowV) * 144 + np * 32 + colV));
                mma16(o[2 * np],     a, &bf[0]);
                mma16(o[2 * np + 1], a, &bf[2]);
            }
        }
        __syncthreads();
    }

    #pragma unroll
    for (int hh = 0; hh < 2; hh++) {
        float inv = 1.0f / l[hh];
        int grow = q0 + rb + hh * 8 + lr;
        #pragma unroll
        for (int ni = 0; ni < 8; ni++) {
            int col = ni * 8 + 2 * lc;
            *(unsigned*)(out + ((size_t)(b * S_ + grow)) * D_ + h * DK_ + col) =
                f2h2(o[ni][hh * 2] * inv, o[ni][hh * 2 + 1] * inv);
        }
    }
}

// --------------------------------- host ---------------------------------------------
extern "C" void kernel_launch(void* const* d_in, const int* in_sizes, int n_in,
                              void* d_out, int out_size) {
    const float* query = (const float*)d_in[0];
    const float* key   = (const float*)d_in[1];
    const float* value = (const float*)d_in[2];
    const int*   mask  = (const int*)d_in[3];
    const float* lAq   = (const float*)d_in[4];
    const float* lBq   = (const float*)d_in[5];
    const float* lAv   = (const float*)d_in[6];
    const float* lBv   = (const float*)d_in[7];
    const float* Wq    = (const float*)d_in[8];
    const float* bq    = (const float*)d_in[9];
    const float* Wk    = (const float*)d_in[10];
    const float* bk    = (const float*)d_in[11];
    const float* Wv    = (const float*)d_in[12];
    const float* bv    = (const float*)d_in[13];
    const float* Wm    = (const float*)d_in[14];
    const float* bm    = (const float*)d_in[15];

    void *pQadjh, *pVadjh, *pkeyh, *pWh, *pqh, *pkh, *pvh, *paoh, *pmw;
    cudaGetSymbolAddress(&pQadjh, g_Qadjh);
    cudaGetSymbolAddress(&pVadjh, g_Vadjh);
    cudaGetSymbolAddress(&pkeyh,  g_keyh);
    cudaGetSymbolAddress(&pWh,    g_Wh);
    cudaGetSymbolAddress(&pqh,    g_qh);
    cudaGetSymbolAddress(&pkh,    g_kh);
    cudaGetSymbolAddress(&pvh,    g_vh);
    cudaGetSymbolAddress(&paoh,   g_aoh);
    cudaGetSymbolAddress(&pmw,    g_mw);

    const __half* Whv = (const __half*)pWh;
    const __half* Whk = Whv + WSZ;
    const __half* Whq = Whv + 2 * WSZ;
    const __half* Whm = Whv + 3 * WSZ;

    // mask pack (independent)
    mask_pack_kernel<<<(B_ * S_ * (S_ / 32)) / 256, 256>>>(mask, (unsigned*)pmw);

    // key + W fp16 converts
    cvt_kernel<<<dim3(N_ * D_ / 4 / 256, 2), 256>>>(
        key, Wv, Wk, Wq, Wm, (__half*)pkeyh, (__half*)pWh);

    // fused LoRA down+up (q and v via gridDim.y)
    cudaFuncSetAttribute(lora_fused_kernel, cudaFuncAttributeMaxDynamicSharedMemorySize, LORA_SMEM);
    lora_fused_kernel<<<dim3(N_ / 16, 2), 128, LORA_SMEM>>>(
        query, value, lAq, lAv, lBq, lBv, (__half*)pQadjh, (__half*)pVadjh);

    // Fused projections (reference's stream swap preserved); q scaled by 0.125*log2e
    Gemm3Args ga;
    ga.A[0] = (const __half*)pQadjh; ga.W[0] = Whv; ga.bias[0] = bv; ga.C[0] = (__half*)pvh; ga.scale[0] = 1.0f;
    ga.A[1] = (const __half*)pkeyh;  ga.W[1] = Whk; ga.bias[1] = bk; ga.C[1] = (__half*)pkh; ga.scale[1] = 1.0f;
    ga.A[2] = (const __half*)pVadjh; ga.W[2] = Whq; ga.bias[2] = bq; ga.C[2] = (__half*)pqh; ga.scale[2] = 0.125f * LOG2E;
    gemm3_kernel<<<dim3(N_ / 128, D_ / 128, 3), 256>>>(ga);

    // Flash attention -> fp16 ao
    cudaFuncSetAttribute(attn_h_kernel, cudaFuncAttributeMaxDynamicSharedMemorySize, ATTN_SMEM);
    attn_h_kernel<<<dim3(S_ / 128, H_, B_), 256, ATTN_SMEM>>>((const unsigned*)pmw, (__half*)paoh);

    // Final: out = ao @ Wm^T + bm (fp32 out)
    gemm1_kernel<<<dim3(N_ / 128, D_ / 128), 256>>>((const __half*)paoh, Whm, bm, (float*)d_out);
}